// round 5
// baseline (speedup 1.0000x reference)
#include <cuda_runtime.h>
#include <math.h>
#include <float.h>
#include <stdint.h>

#define SEQ    1024
#define DMODEL 1024
#define NHEAD  16
#define DHEAD  64
#define NBATCH 2
#define POS2   512
#define GTOT   (NBATCH * SEQ)   // 2048

// ---------------- scratch ----------------------------------------------------
__device__ float g_Q[NBATCH * SEQ * DMODEL];
__device__ float g_K[NBATCH * SEQ * DMODEL];
__device__ float g_V[NBATCH * SEQ * DMODEL];
__device__ float g_PQ[POS2 * DMODEL];
__device__ float g_PK[POS2 * DMODEL];
__device__ float g_c2pT[NHEAD * POS2 * GTOT];   // [h][bucket][g]  (transposed!)
__device__ float g_p2cT[NHEAD * POS2 * GTOT];   // [h][bucket][g]
__device__ int2  g_idx2[2047];                  // (idxC, idxP)
__device__ unsigned g_pmask[NBATCH * SEQ * (SEQ / 32)];

// ---------------- helpers ----------------------------------------------------
__device__ __forceinline__ uint32_t f2tf32(float x) {
    uint32_t r;
    asm("cvt.rna.tf32.f32 %0, %1;" : "=r"(r) : "f"(x));
    return r;
}
__device__ __forceinline__ void mma_tf32(float c[4], const uint32_t a[4], const uint32_t b[2]) {
    asm volatile(
        "mma.sync.aligned.m16n8k8.row.col.f32.tf32.tf32.f32 "
        "{%0,%1,%2,%3}, {%4,%5,%6,%7}, {%8,%9}, {%0,%1,%2,%3};"
        : "+f"(c[0]), "+f"(c[1]), "+f"(c[2]), "+f"(c[3])
        : "r"(a[0]), "r"(a[1]), "r"(a[2]), "r"(a[3]), "r"(b[0]), "r"(b[1]));
}

// ---------------- log-bucket tables ------------------------------------------
__device__ __forceinline__ int log_bucket(int rel) {
    const int mid = 128;
    float absp;
    if (rel < mid && rel > -mid) absp = (float)(mid - 1);
    else absp = fabsf((float)rel);
    if (absp <= (float)mid) return rel;
    float lp = ceilf(logf(absp / 128.0f) / 1.3843393291f * 127.0f) + 128.0f;
    float sgn = (rel > 0) ? 1.0f : ((rel < 0) ? -1.0f : 0.0f);
    return (int)(lp * sgn);
}
__global__ void init_tables_kernel() {
    int t = blockIdx.x * blockDim.x + threadIdx.x;
    if (t < 2047) {
        int delta = t - 1023;
        int bC = log_bucket(delta);
        int bP = log_bucket(-delta);
        int2 v;
        v.x = min(max(bC + 256, 0), 511);
        v.y = min(max(-bP + 256, 0), 511);
        g_idx2[t] = v;
    }
}

// ---------------- mask bit-pack ----------------------------------------------
__global__ void pack_mask_kernel(const int* __restrict__ mask) {
    int idx = blockIdx.x * 256 + threadIdx.x;
    int v = mask[idx];
    unsigned bal = __ballot_sync(0xffffffffu, v != 0);
    if ((threadIdx.x & 31) == 0) g_pmask[idx >> 5] = bal;
}

// ================= TF32 GEMM: projections (QKV + positional merged) ==========
#define QKV_AS_STRIDE 36
#define QKV_BS_STRIDE 136
#define QKV_ABUF (128 * QKV_AS_STRIDE)
#define QKV_BBUF (32 * QKV_BS_STRIDE)

__global__ __launch_bounds__(256) void gemm_proj_tf32(
    const float* __restrict__ hidden, const float* __restrict__ rel,
    const float* __restrict__ Wq, const float* __restrict__ Wk, const float* __restrict__ Wv,
    const float* __restrict__ bq, const float* __restrict__ bk, const float* __restrict__ bv) {

    int z = blockIdx.z;
    int y = blockIdx.y;
    const float* A;
    float* C;
    int m0;
    if (y < 16) {
        A = hidden; m0 = y * 128;
        C = (z == 0) ? g_Q : (z == 1) ? g_K : g_V;
    } else {
        if (z == 2) return;
        A = rel; m0 = (y - 16) * 128;
        C = (z == 0) ? g_PQ : g_PK;
    }
    const float* W = (z == 0) ? Wq : (z == 1) ? Wk : Wv;
    const float* bias = (z == 0) ? bq : (z == 1) ? bk : bv;

    extern __shared__ uint32_t smu[];
    uint32_t* As = smu;
    uint32_t* Bs = smu + 2 * QKV_ABUF;

    int tid = threadIdx.x;
    int lane = tid & 31, wid = tid >> 5;
    int wm = (wid >> 2) * 64, wn = (wid & 3) * 32;
    int n0 = blockIdx.x * 128;

    int arow = tid >> 3, acol = (tid & 7) * 4;
    int brow = tid >> 5, bcol = (tid & 31) * 4;

    float4 ra[4], rb[4];
    float acc[16][4];
    #pragma unroll
    for (int t = 0; t < 16; t++)
        #pragma unroll
        for (int j = 0; j < 4; j++) acc[t][j] = 0.0f;

    #pragma unroll
    for (int p = 0; p < 4; p++) {
        ra[p] = *(const float4*)&A[(size_t)(m0 + arow + p * 32) * 1024 + acol];
        rb[p] = *(const float4*)&W[(size_t)(brow + p * 8) * 1024 + n0 + bcol];
    }
    #pragma unroll
    for (int p = 0; p < 4; p++) {
        uint32_t* d = &As[(arow + p * 32) * QKV_AS_STRIDE + acol];
        d[0] = f2tf32(ra[p].x); d[1] = f2tf32(ra[p].y); d[2] = f2tf32(ra[p].z); d[3] = f2tf32(ra[p].w);
        uint32_t* e = &Bs[(brow + p * 8) * QKV_BS_STRIDE + bcol];
        e[0] = f2tf32(rb[p].x); e[1] = f2tf32(rb[p].y); e[2] = f2tf32(rb[p].z); e[3] = f2tf32(rb[p].w);
    }
    __syncthreads();

    int buf = 0;
    for (int kk = 32; kk <= 1024; kk += 32) {
        if (kk < 1024) {
            #pragma unroll
            for (int p = 0; p < 4; p++) {
                ra[p] = *(const float4*)&A[(size_t)(m0 + arow + p * 32) * 1024 + kk + acol];
                rb[p] = *(const float4*)&W[(size_t)(kk + brow + p * 8) * 1024 + n0 + bcol];
            }
        }
        const uint32_t* Ab = &As[buf * QKV_ABUF];
        const uint32_t* Bb = &Bs[buf * QKV_BBUF];
        #pragma unroll
        for (int ks = 0; ks < 4; ks++) {
            int kb = ks * 8;
            uint32_t af[4][4], bf[4][2];
            #pragma unroll
            for (int i = 0; i < 4; i++) {
                int r = wm + i * 16 + (lane >> 2);
                int c = kb + (lane & 3);
                af[i][0] = Ab[r * QKV_AS_STRIDE + c];
                af[i][1] = Ab[(r + 8) * QKV_AS_STRIDE + c];
                af[i][2] = Ab[r * QKV_AS_STRIDE + c + 4];
                af[i][3] = Ab[(r + 8) * QKV_AS_STRIDE + c + 4];
            }
            #pragma unroll
            for (int j = 0; j < 4; j++) {
                int r = kb + (lane & 3);
                int c = wn + j * 8 + (lane >> 2);
                bf[j][0] = Bb[r * QKV_BS_STRIDE + c];
                bf[j][1] = Bb[(r + 4) * QKV_BS_STRIDE + c];
            }
            #pragma unroll
            for (int i = 0; i < 4; i++)
                #pragma unroll
                for (int j = 0; j < 4; j++)
                    mma_tf32(acc[i * 4 + j], af[i], bf[j]);
        }
        __syncthreads();
        if (kk < 1024) {
            buf ^= 1;
            #pragma unroll
            for (int p = 0; p < 4; p++) {
                uint32_t* d = &As[buf * QKV_ABUF + (arow + p * 32) * QKV_AS_STRIDE + acol];
                d[0] = f2tf32(ra[p].x); d[1] = f2tf32(ra[p].y); d[2] = f2tf32(ra[p].z); d[3] = f2tf32(ra[p].w);
                uint32_t* e = &Bs[buf * QKV_BBUF + (brow + p * 8) * QKV_BS_STRIDE + bcol];
                e[0] = f2tf32(rb[p].x); e[1] = f2tf32(rb[p].y); e[2] = f2tf32(rb[p].z); e[3] = f2tf32(rb[p].w);
            }
            __syncthreads();
        }
    }

    #pragma unroll
    for (int i = 0; i < 4; i++) {
        #pragma unroll
        for (int j = 0; j < 4; j++) {
            int r = m0 + wm + i * 16 + (lane >> 2);
            int c = n0 + wn + j * 8 + (lane & 3) * 2;
            float bx = bias[c], by = bias[c + 1];
            float2 v0 = {acc[i * 4 + j][0] + bx, acc[i * 4 + j][1] + by};
            *(float2*)&C[(size_t)r * 1024 + c] = v0;
            float2 v1 = {acc[i * 4 + j][2] + bx, acc[i * 4 + j][3] + by};
            *(float2*)&C[(size_t)(r + 8) * 1024 + c] = v1;
        }
    }
}

// ============ TF32 per-head positional GEMM (bucket-major output) ============
// c2pT[h][p][g] = sum_d PK[p,h,d] * Q[g,h,d]   (z<16)
// p2cT[h][p][g] = sum_d PQ[p,h,d] * K[g,h,d]   (z>=16)
// M = bucket (512), N = g (2048). Tile 128(M) x 64(N), K=64 single-shot.
#define ABT_AS_STRIDE 68
#define ABT_BS_STRIDE 136

__global__ __launch_bounds__(256) void gemm_pos_tf32() {
    int z = blockIdx.z;
    int h = z & 15;
    const float* Ap = (z < 16) ? g_PK : g_PQ;   // [512][1024], M rows
    const float* Bp = (z < 16) ? g_Q  : g_K;    // [2048][1024], N rows
    float* Cp = (z < 16) ? g_c2pT : g_p2cT;

    extern __shared__ uint32_t smu[];
    uint32_t* As = smu;                       // [128][68]   (M x d)
    uint32_t* Bs = smu + 128 * ABT_AS_STRIDE; // [64][136]   ([d][n])

    int tid = threadIdx.x;
    int lane = tid & 31, wid = tid >> 5;
    int wm = (wid >> 1) * 32, wn = (wid & 1) * 32;
    int r0 = blockIdx.y * 128;   // bucket tile
    int n0 = blockIdx.x * 64;    // g tile

    {
        int row = tid >> 4, col = (tid & 15) * 4;
        #pragma unroll
        for (int p = 0; p < 8; p++) {
            float4 v = *(const float4*)&Ap[(size_t)(r0 + row + p * 16) * 1024 + h * 64 + col];
            uint32_t* d = &As[(row + p * 16) * ABT_AS_STRIDE + col];
            d[0] = f2tf32(v.x); d[1] = f2tf32(v.y); d[2] = f2tf32(v.z); d[3] = f2tf32(v.w);
        }
    }
    {
        int pp = tid & 63, d4 = (tid >> 6) * 4;
        #pragma unroll
        for (int ps = 0; ps < 4; ps++) {
            int d = d4 + ps * 16;
            float4 v = *(const float4*)&Bp[(size_t)(n0 + pp) * 1024 + h * 64 + d];
            Bs[(d + 0) * ABT_BS_STRIDE + pp] = f2tf32(v.x);
            Bs[(d + 1) * ABT_BS_STRIDE + pp] = f2tf32(v.y);
            Bs[(d + 2) * ABT_BS_STRIDE + pp] = f2tf32(v.z);
            Bs[(d + 3) * ABT_BS_STRIDE + pp] = f2tf32(v.w);
        }
    }
    __syncthreads();

    float acc[8][4];
    #pragma unroll
    for (int t = 0; t < 8; t++)
        #pragma unroll
        for (int j = 0; j < 4; j++) acc[t][j] = 0.0f;

    #pragma unroll
    for (int ks = 0; ks < 8; ks++) {
        int kb = ks * 8;
        uint32_t af[2][4], bf[4][2];
        #pragma unroll
        for (int i = 0; i < 2; i++) {
            int r = wm + i * 16 + (lane >> 2);
            int c = kb + (lane & 3);
            af[i][0] = As[r * ABT_AS_STRIDE + c];
            af[i][1] = As[(r + 8) * ABT_AS_STRIDE + c];
            af[i][2] = As[r * ABT_AS_STRIDE + c + 4];
            af[i][3] = As[(r + 8) * ABT_AS_STRIDE + c + 4];
        }
        #pragma unroll
        for (int j = 0; j < 4; j++) {
            int r = kb + (lane & 3);
            int c = wn + j * 8 + (lane >> 2);
            bf[j][0] = Bs[r * ABT_BS_STRIDE + c];
            bf[j][1] = Bs[(r + 4) * ABT_BS_STRIDE + c];
        }
        #pragma unroll
        for (int i = 0; i < 2; i++)
            #pragma unroll
            for (int j = 0; j < 4; j++)
                mma_tf32(acc[i * 4 + j], af[i], bf[j]);
    }

    #pragma unroll
    for (int i = 0; i < 2; i++) {
        #pragma unroll
        for (int j = 0; j < 4; j++) {
            int r = r0 + wm + i * 16 + (lane >> 2);          // bucket index
            int c = n0 + wn + j * 8 + (lane & 3) * 2;        // g index
            float2 v0 = {acc[i * 4 + j][0], acc[i * 4 + j][1]};
            *(float2*)&Cp[((size_t)h * POS2 + r) * GTOT + c] = v0;
            float2 v1 = {acc[i * 4 + j][2], acc[i * 4 + j][3]};
            *(float2*)&Cp[((size_t)h * POS2 + r + 8) * GTOT + c] = v1;
        }
    }
}

// ================= tensor-core flash attention (v3) ==========================
// 64x64 tiles, 128 threads, 4 CTAs/SM; bias tile rebuilt per k-tile from
// bucket-major c2pT/p2cT with coalesced diagonal loads; overlays Ks smem.
#define AQS 68
#define AVS 72
#define BSTR 66   // bias smem row stride (floats)

__global__ __launch_bounds__(128, 4) void attn_tc_kernel(float* __restrict__ out) {
    extern __shared__ uint32_t sm[];
    uint32_t* Qs = sm;              // [64][68]
    uint32_t* Ks = Qs + 64 * AQS;   // [64][68]  (reused as bias tile)
    uint32_t* Vs = Ks + 64 * AQS;   // [64][72]
    float* BiasS = (float*)Ks;      // [64][66]  overlays Ks after S-mma

    int tid = threadIdx.x;
    int lane = tid & 31, wid = tid >> 5;
    int bh = blockIdx.y;
    int b = bh >> 4, h = bh & 15;
    int q0 = blockIdx.x * 64;

    // load Q tile (tf32)
    #pragma unroll
    for (int it = 0; it < 8; it++) {
        int idx = tid + it * 128;
        int row = idx >> 4, col = (idx & 15) * 4;
        float4 v = *(const float4*)&g_Q[(size_t)(b * SEQ + q0 + row) * 1024 + h * 64 + col];
        uint32_t* d = &Qs[row * AQS + col];
        d[0] = f2tf32(v.x); d[1] = f2tf32(v.y); d[2] = f2tf32(v.z); d[3] = f2tf32(v.w);
    }

    int qd = lane & 3, e = qd & 1;
    int srcA = (lane & ~3) | (qd >> 1);
    int srcB = srcA + 2;

    int r0l = wid * 16 + (lane >> 2);
    int row0 = q0 + r0l, row1 = row0 + 8;
    const unsigned* pm0 = &g_pmask[(size_t)(b * SEQ + row0) * 32];
    const unsigned* pm1 = &g_pmask[(size_t)(b * SEQ + row1) * 32];
    const float* c2pb = g_c2pT + ((size_t)h * POS2) * GTOT + b * SEQ;
    const float* p2cb = g_p2cT + ((size_t)h * POS2) * GTOT + b * SEQ;

    float m_run0 = -FLT_MAX, m_run1 = -FLT_MAX, l_run0 = 0.0f, l_run1 = 0.0f;
    float O[8][4];
    #pragma unroll
    for (int f = 0; f < 8; f++)
        #pragma unroll
        for (int j = 0; j < 4; j++) O[f][j] = 0.0f;

    const float inv_scale = 0.07216878364870323f; // 1/sqrt(64*3)

    for (int k0 = 0; k0 < SEQ; k0 += 64) {
        __syncthreads();
        #pragma unroll
        for (int it = 0; it < 8; it++) {
            int idx = tid + it * 128;
            int row = idx >> 4, col = (idx & 15) * 4;
            float4 kv = *(const float4*)&g_K[(size_t)(b * SEQ + k0 + row) * 1024 + h * 64 + col];
            float4 vv = *(const float4*)&g_V[(size_t)(b * SEQ + k0 + row) * 1024 + h * 64 + col];
            uint32_t* dk = &Ks[row * AQS + col];
            dk[0] = f2tf32(kv.x); dk[1] = f2tf32(kv.y); dk[2] = f2tf32(kv.z); dk[3] = f2tf32(kv.w);
            uint32_t* dv = &Vs[row * AVS + col];
            dv[0] = f2tf32(vv.x); dv[1] = f2tf32(vv.y); dv[2] = f2tf32(vv.z); dv[3] = f2tf32(vv.w);
        }
        __syncthreads();

        // ---- S = Q K^T
        float sa[8][4];
        #pragma unroll
        for (int f = 0; f < 8; f++)
            #pragma unroll
            for (int j = 0; j < 4; j++) sa[f][j] = 0.0f;

        #pragma unroll
        for (int ks = 0; ks < 8; ks++) {
            int kb = ks * 8;
            uint32_t a[4];
            a[0] = Qs[r0l * AQS + kb + qd];
            a[1] = Qs[(r0l + 8) * AQS + kb + qd];
            a[2] = Qs[r0l * AQS + kb + 4 + qd];
            a[3] = Qs[(r0l + 8) * AQS + kb + 4 + qd];
            #pragma unroll
            for (int nf = 0; nf < 8; nf++) {
                int n = nf * 8 + (lane >> 2);
                uint32_t bf[2];
                bf[0] = Ks[n * AQS + kb + qd];
                bf[1] = Ks[n * AQS + kb + 4 + qd];
                mma_tf32(sa[nf], a, bf);
            }
        }

        __syncthreads();   // Ks reads done; safe to overwrite with bias tile

        // ---- build 64x64 bias tile: diagonals are constant-bucket ⇒ coalesced
        {
            int base = q0 - k0;
            for (int t = wid; t < 127; t += 4) {
                int dl = t - 63;                 // q_l - k_l
                int2 ix = g_idx2[base + dl + 1023];
                const float* cr = c2pb + (size_t)ix.x * GTOT + q0;
                const float* pr = p2cb + (size_t)ix.y * GTOT + k0;
                int qs = dl > 0 ? dl : 0;
                int len = 64 - (dl < 0 ? -dl : dl);
                #pragma unroll 2
                for (int s = 0; s < len; s += 32) {
                    int o = s + lane;
                    if (o < len) {
                        int q_l = qs + o;
                        int k_l = q_l - dl;
                        BiasS[q_l * BSTR + k_l] = cr[q_l] + pr[k_l];
                    }
                }
            }
        }
        __syncthreads();

        // ---- masks (bit-packed)
        unsigned m0a = pm0[k0 >> 5], m0b = pm0[(k0 >> 5) + 1];
        unsigned m1a = pm1[k0 >> 5], m1b = pm1[(k0 >> 5) + 1];

        // ---- bias + scale + mask
        float s0max = -FLT_MAX, s1max = -FLT_MAX;
        #pragma unroll
        for (int nf = 0; nf < 8; nf++) {
            int cb = nf * 8 + 2 * qd;
            float2 b0 = *(float2*)&BiasS[r0l * BSTR + cb];
            float2 b1 = *(float2*)&BiasS[(r0l + 8) * BSTR + cb];
            #pragma unroll
            for (int j = 0; j < 2; j++) {
                int kl = cb + j;
                float v0 = (sa[nf][j]     + (j ? b0.y : b0.x)) * inv_scale;
                float v1 = (sa[nf][j + 2] + (j ? b1.y : b1.x)) * inv_scale;
                unsigned w0 = (kl & 32) ? m0b : m0a;
                unsigned w1 = (kl & 32) ? m1b : m1a;
                v0 = ((w0 >> (kl & 31)) & 1u) ? v0 : -FLT_MAX;
                v1 = ((w1 >> (kl & 31)) & 1u) ? v1 : -FLT_MAX;
                sa[nf][j] = v0; sa[nf][j + 2] = v1;
                s0max = fmaxf(s0max, v0); s1max = fmaxf(s1max, v1);
            }
        }

        // ---- online softmax (row over quad)
        s0max = fmaxf(s0max, __shfl_xor_sync(0xffffffffu, s0max, 1));
        s0max = fmaxf(s0max, __shfl_xor_sync(0xffffffffu, s0max, 2));
        s1max = fmaxf(s1max, __shfl_xor_sync(0xffffffffu, s1max, 1));
        s1max = fmaxf(s1max, __shfl_xor_sync(0xffffffffu, s1max, 2));
        float m0n = fmaxf(m_run0, s0max), m1n = fmaxf(m_run1, s1max);
        float a0 = __expf(m_run0 - m0n), a1 = __expf(m_run1 - m1n);
        float psum0 = 0.0f, psum1 = 0.0f;
        #pragma unroll
        for (int nf = 0; nf < 8; nf++) {
            sa[nf][0] = __expf(sa[nf][0] - m0n);
            sa[nf][1] = __expf(sa[nf][1] - m0n);
            sa[nf][2] = __expf(sa[nf][2] - m1n);
            sa[nf][3] = __expf(sa[nf][3] - m1n);
            psum0 += sa[nf][0] + sa[nf][1];
            psum1 += sa[nf][2] + sa[nf][3];
        }
        psum0 += __shfl_xor_sync(0xffffffffu, psum0, 1);
        psum0 += __shfl_xor_sync(0xffffffffu, psum0, 2);
        psum1 += __shfl_xor_sync(0xffffffffu, psum1, 1);
        psum1 += __shfl_xor_sync(0xffffffffu, psum1, 2);
        l_run0 = l_run0 * a0 + psum0;
        l_run1 = l_run1 * a1 + psum1;
        m_run0 = m0n; m_run1 = m1n;
        #pragma unroll
        for (int f = 0; f < 8; f++) {
            O[f][0] *= a0; O[f][1] *= a0; O[f][2] *= a1; O[f][3] *= a1;
        }

        // ---- O += P V : transpose P fragments via quad shfl (no smem)
        #pragma unroll
        for (int ks = 0; ks < 8; ks++) {
            float x0 = __shfl_sync(0xffffffffu, sa[ks][0], srcA);
            float x1 = __shfl_sync(0xffffffffu, sa[ks][1], srcA);
            float x2 = __shfl_sync(0xffffffffu, sa[ks][2], srcA);
            float x3 = __shfl_sync(0xffffffffu, sa[ks][3], srcA);
            float y0 = __shfl_sync(0xffffffffu, sa[ks][0], srcB);
            float y1 = __shfl_sync(0xffffffffu, sa[ks][1], srcB);
            float y2 = __shfl_sync(0xffffffffu, sa[ks][2], srcB);
            float y3 = __shfl_sync(0xffffffffu, sa[ks][3], srcB);
            uint32_t a[4];
            a[0] = f2tf32(e ? x1 : x0);
            a[1] = f2tf32(e ? x3 : x2);
            a[2] = f2tf32(e ? y1 : y0);
            a[3] = f2tf32(e ? y3 : y2);
            int kb = ks * 8;
            #pragma unroll
            for (int nf = 0; nf < 8; nf++) {
                int n = nf * 8 + (lane >> 2);
                uint32_t bf[2];
                bf[0] = Vs[(kb + qd) * AVS + n];
                bf[1] = Vs[(kb + 4 + qd) * AVS + n];
                mma_tf32(O[nf], a, bf);
            }
        }
    }

    // ---- epilogue
    float invl0 = (m_run0 == -FLT_MAX) ? 0.0f : (1.0f / l_run0);
    float invl1 = (m_run1 == -FLT_MAX) ? 0.0f : (1.0f / l_run1);
    #pragma unroll
    for (int nf = 0; nf < 8; nf++) {
        int d = nf * 8 + 2 * qd;
        float2 o0 = {O[nf][0] * invl0, O[nf][1] * invl0};
        *(float2*)&out[(size_t)(b * SEQ + row0) * 1024 + h * 64 + d] = o0;
        float2 o1 = {O[nf][2] * invl1, O[nf][3] * invl1};
        *(float2*)&out[(size_t)(b * SEQ + row1) * 1024 + h * 64 + d] = o1;
    }
}

// ---------------- launch ----------------------------------------------------
extern "C" void kernel_launch(void* const* d_in, const int* in_sizes, int n_in,
                              void* d_out, int out_size) {
    const float* hidden = (const float*)d_in[0];
    const int*   mask   = (const int*)d_in[1];
    const float* rel    = (const float*)d_in[2];
    const float* Wq     = (const float*)d_in[3];
    const float* bq     = (const float*)d_in[4];
    const float* Wk     = (const float*)d_in[5];
    const float* bk     = (const float*)d_in[6];
    const float* Wv     = (const float*)d_in[7];
    const float* bv     = (const float*)d_in[8];
    float* out = (float*)d_out;

    init_tables_kernel<<<8, 256>>>();
    pack_mask_kernel<<<NBATCH * SEQ * SEQ / 256, 256>>>(mask);

    int smem_qkv = (2 * QKV_ABUF + 2 * QKV_BBUF) * (int)sizeof(uint32_t);
    cudaFuncSetAttribute(gemm_proj_tf32, cudaFuncAttributeMaxDynamicSharedMemorySize, smem_qkv);
    gemm_proj_tf32<<<dim3(8, 20, 3), 256, smem_qkv>>>(
        hidden, rel, Wq, Wk, Wv, bq, bk, bv);

    int smem_abt = (128 * ABT_AS_STRIDE + 64 * ABT_BS_STRIDE) * (int)sizeof(uint32_t);
    cudaFuncSetAttribute(gemm_pos_tf32, cudaFuncAttributeMaxDynamicSharedMemorySize, smem_abt);
    gemm_pos_tf32<<<dim3(GTOT / 64, POS2 / 128, 32), 256, smem_abt>>>();

    int smem_attn = (2 * 64 * AQS + 64 * AVS) * (int)sizeof(uint32_t);
    cudaFuncSetAttribute(attn_tc_kernel, cudaFuncAttributeMaxDynamicSharedMemorySize, smem_attn);
    attn_tc_kernel<<<dim3(SEQ / 64, NBATCH * NHEAD), 128, smem_attn>>>(out);
}

// round 6
// speedup vs baseline: 1.6138x; 1.6138x over previous
#include <cuda_runtime.h>
#include <math.h>
#include <float.h>
#include <stdint.h>

#define SEQ    1024
#define DMODEL 1024
#define NHEAD  16
#define DHEAD  64
#define NBATCH 2
#define POS2   512

// ---------------- scratch ----------------------------------------------------
__device__ float g_Q[NBATCH * SEQ * DMODEL];
__device__ float g_K[NBATCH * SEQ * DMODEL];
__device__ float g_V[NBATCH * SEQ * DMODEL];
__device__ float g_PQ[POS2 * DMODEL];
__device__ float g_PK[POS2 * DMODEL];
__device__ float g_c2p[NHEAD * NBATCH * SEQ * POS2];   // [h][g][bucket]
__device__ float g_p2c[NHEAD * NBATCH * SEQ * POS2];   // [h][g][bucket]
__device__ int2  g_idx2[2047];                         // (idxC, idxP)
__device__ unsigned g_pmask[NBATCH * SEQ * (SEQ / 32)];

// ---------------- helpers ----------------------------------------------------
__device__ __forceinline__ uint32_t f2tf32(float x) {
    uint32_t r;
    asm("cvt.rna.tf32.f32 %0, %1;" : "=r"(r) : "f"(x));
    return r;
}
__device__ __forceinline__ void mma_tf32(float c[4], const uint32_t a[4], const uint32_t b[2]) {
    asm volatile(
        "mma.sync.aligned.m16n8k8.row.col.f32.tf32.tf32.f32 "
        "{%0,%1,%2,%3}, {%4,%5,%6,%7}, {%8,%9}, {%0,%1,%2,%3};"
        : "+f"(c[0]), "+f"(c[1]), "+f"(c[2]), "+f"(c[3])
        : "r"(a[0]), "r"(a[1]), "r"(a[2]), "r"(a[3]), "r"(b[0]), "r"(b[1]));
}

// ---------------- log-bucket tables ------------------------------------------
__device__ __forceinline__ int log_bucket(int rel) {
    const int mid = 128;
    float absp;
    if (rel < mid && rel > -mid) absp = (float)(mid - 1);
    else absp = fabsf((float)rel);
    if (absp <= (float)mid) return rel;
    float lp = ceilf(logf(absp / 128.0f) / 1.3843393291f * 127.0f) + 128.0f;
    float sgn = (rel > 0) ? 1.0f : ((rel < 0) ? -1.0f : 0.0f);
    return (int)(lp * sgn);
}
__global__ void init_tables_kernel() {
    int t = blockIdx.x * blockDim.x + threadIdx.x;
    if (t < 2047) {
        int delta = t - 1023;
        int bC = log_bucket(delta);
        int bP = log_bucket(-delta);
        int2 v;
        v.x = min(max(bC + 256, 0), 511);
        v.y = min(max(-bP + 256, 0), 511);
        g_idx2[t] = v;
    }
}

// ---------------- mask bit-pack ----------------------------------------------
__global__ void pack_mask_kernel(const int* __restrict__ mask) {
    int idx = blockIdx.x * 256 + threadIdx.x;
    int v = mask[idx];
    unsigned bal = __ballot_sync(0xffffffffu, v != 0);
    if ((threadIdx.x & 31) == 0) g_pmask[idx >> 5] = bal;
}

// ================= TF32 GEMM: projections (QKV + positional merged) ==========
#define QKV_AS_STRIDE 36
#define QKV_BS_STRIDE 136
#define QKV_ABUF (128 * QKV_AS_STRIDE)
#define QKV_BBUF (32 * QKV_BS_STRIDE)

__global__ __launch_bounds__(256) void gemm_proj_tf32(
    const float* __restrict__ hidden, const float* __restrict__ rel,
    const float* __restrict__ Wq, const float* __restrict__ Wk, const float* __restrict__ Wv,
    const float* __restrict__ bq, const float* __restrict__ bk, const float* __restrict__ bv) {

    int z = blockIdx.z;
    int y = blockIdx.y;
    const float* A;
    float* C;
    int m0;
    if (y < 16) {
        A = hidden; m0 = y * 128;
        C = (z == 0) ? g_Q : (z == 1) ? g_K : g_V;
    } else {
        if (z == 2) return;
        A = rel; m0 = (y - 16) * 128;
        C = (z == 0) ? g_PQ : g_PK;
    }
    const float* W = (z == 0) ? Wq : (z == 1) ? Wk : Wv;
    const float* bias = (z == 0) ? bq : (z == 1) ? bk : bv;

    extern __shared__ uint32_t smu[];
    uint32_t* As = smu;
    uint32_t* Bs = smu + 2 * QKV_ABUF;

    int tid = threadIdx.x;
    int lane = tid & 31, wid = tid >> 5;
    int wm = (wid >> 2) * 64, wn = (wid & 3) * 32;
    int n0 = blockIdx.x * 128;

    int arow = tid >> 3, acol = (tid & 7) * 4;
    int brow = tid >> 5, bcol = (tid & 31) * 4;

    float4 ra[4], rb[4];
    float acc[16][4];
    #pragma unroll
    for (int t = 0; t < 16; t++)
        #pragma unroll
        for (int j = 0; j < 4; j++) acc[t][j] = 0.0f;

    #pragma unroll
    for (int p = 0; p < 4; p++) {
        ra[p] = *(const float4*)&A[(size_t)(m0 + arow + p * 32) * 1024 + acol];
        rb[p] = *(const float4*)&W[(size_t)(brow + p * 8) * 1024 + n0 + bcol];
    }
    #pragma unroll
    for (int p = 0; p < 4; p++) {
        uint32_t* d = &As[(arow + p * 32) * QKV_AS_STRIDE + acol];
        d[0] = f2tf32(ra[p].x); d[1] = f2tf32(ra[p].y); d[2] = f2tf32(ra[p].z); d[3] = f2tf32(ra[p].w);
        uint32_t* e = &Bs[(brow + p * 8) * QKV_BS_STRIDE + bcol];
        e[0] = f2tf32(rb[p].x); e[1] = f2tf32(rb[p].y); e[2] = f2tf32(rb[p].z); e[3] = f2tf32(rb[p].w);
    }
    __syncthreads();

    int buf = 0;
    for (int kk = 32; kk <= 1024; kk += 32) {
        if (kk < 1024) {
            #pragma unroll
            for (int p = 0; p < 4; p++) {
                ra[p] = *(const float4*)&A[(size_t)(m0 + arow + p * 32) * 1024 + kk + acol];
                rb[p] = *(const float4*)&W[(size_t)(kk + brow + p * 8) * 1024 + n0 + bcol];
            }
        }
        const uint32_t* Ab = &As[buf * QKV_ABUF];
        const uint32_t* Bb = &Bs[buf * QKV_BBUF];
        #pragma unroll
        for (int ks = 0; ks < 4; ks++) {
            int kb = ks * 8;
            uint32_t af[4][4], bf[4][2];
            #pragma unroll
            for (int i = 0; i < 4; i++) {
                int r = wm + i * 16 + (lane >> 2);
                int c = kb + (lane & 3);
                af[i][0] = Ab[r * QKV_AS_STRIDE + c];
                af[i][1] = Ab[(r + 8) * QKV_AS_STRIDE + c];
                af[i][2] = Ab[r * QKV_AS_STRIDE + c + 4];
                af[i][3] = Ab[(r + 8) * QKV_AS_STRIDE + c + 4];
            }
            #pragma unroll
            for (int j = 0; j < 4; j++) {
                int r = kb + (lane & 3);
                int c = wn + j * 8 + (lane >> 2);
                bf[j][0] = Bb[r * QKV_BS_STRIDE + c];
                bf[j][1] = Bb[(r + 4) * QKV_BS_STRIDE + c];
            }
            #pragma unroll
            for (int i = 0; i < 4; i++)
                #pragma unroll
                for (int j = 0; j < 4; j++)
                    mma_tf32(acc[i * 4 + j], af[i], bf[j]);
        }
        __syncthreads();
        if (kk < 1024) {
            buf ^= 1;
            #pragma unroll
            for (int p = 0; p < 4; p++) {
                uint32_t* d = &As[buf * QKV_ABUF + (arow + p * 32) * QKV_AS_STRIDE + acol];
                d[0] = f2tf32(ra[p].x); d[1] = f2tf32(ra[p].y); d[2] = f2tf32(ra[p].z); d[3] = f2tf32(ra[p].w);
                uint32_t* e = &Bs[buf * QKV_BBUF + (brow + p * 8) * QKV_BS_STRIDE + bcol];
                e[0] = f2tf32(rb[p].x); e[1] = f2tf32(rb[p].y); e[2] = f2tf32(rb[p].z); e[3] = f2tf32(rb[p].w);
            }
            __syncthreads();
        }
    }

    #pragma unroll
    for (int i = 0; i < 4; i++) {
        #pragma unroll
        for (int j = 0; j < 4; j++) {
            int r = m0 + wm + i * 16 + (lane >> 2);
            int c = n0 + wn + j * 8 + (lane & 3) * 2;
            float bx = bias[c], by = bias[c + 1];
            float2 v0 = {acc[i * 4 + j][0] + bx, acc[i * 4 + j][1] + by};
            *(float2*)&C[(size_t)r * 1024 + c] = v0;
            float2 v1 = {acc[i * 4 + j][2] + bx, acc[i * 4 + j][3] + by};
            *(float2*)&C[(size_t)(r + 8) * 1024 + c] = v1;
        }
    }
}

// ============ TF32 per-head A@B^T (c2p_att / p2c_att), g-major output ========
#define ABT_AS_STRIDE 68
#define ABT_BS_STRIDE 136

__global__ __launch_bounds__(256) void gemm_abT_tf32() {
    int z = blockIdx.z;
    int h = z & 15;
    const float* Ap = (z < 16) ? g_Q : g_K;
    const float* Bp = (z < 16) ? g_PK : g_PQ;
    float* Cp = (z < 16) ? g_c2p : g_p2c;

    extern __shared__ uint32_t smu[];
    uint32_t* As = smu;
    uint32_t* Bs = smu + 128 * ABT_AS_STRIDE;

    int tid = threadIdx.x;
    int lane = tid & 31, wid = tid >> 5;
    int wm = (wid >> 1) * 32, wn = (wid & 1) * 32;
    int r0 = blockIdx.y * 128, p0 = blockIdx.x * 64;

    {
        int row = tid >> 4, col = (tid & 15) * 4;
        #pragma unroll
        for (int p = 0; p < 8; p++) {
            float4 v = *(const float4*)&Ap[(size_t)(r0 + row + p * 16) * 1024 + h * 64 + col];
            uint32_t* d = &As[(row + p * 16) * ABT_AS_STRIDE + col];
            d[0] = f2tf32(v.x); d[1] = f2tf32(v.y); d[2] = f2tf32(v.z); d[3] = f2tf32(v.w);
        }
    }
    {
        int pp = tid & 63, d4 = (tid >> 6) * 4;
        #pragma unroll
        for (int ps = 0; ps < 4; ps++) {
            int d = d4 + ps * 16;
            float4 v = *(const float4*)&Bp[(size_t)(p0 + pp) * 1024 + h * 64 + d];
            Bs[(d + 0) * ABT_BS_STRIDE + pp] = f2tf32(v.x);
            Bs[(d + 1) * ABT_BS_STRIDE + pp] = f2tf32(v.y);
            Bs[(d + 2) * ABT_BS_STRIDE + pp] = f2tf32(v.z);
            Bs[(d + 3) * ABT_BS_STRIDE + pp] = f2tf32(v.w);
        }
    }
    __syncthreads();

    float acc[8][4];
    #pragma unroll
    for (int t = 0; t < 8; t++)
        #pragma unroll
        for (int j = 0; j < 4; j++) acc[t][j] = 0.0f;

    #pragma unroll
    for (int ks = 0; ks < 8; ks++) {
        int kb = ks * 8;
        uint32_t af[2][4], bf[4][2];
        #pragma unroll
        for (int i = 0; i < 2; i++) {
            int r = wm + i * 16 + (lane >> 2);
            int c = kb + (lane & 3);
            af[i][0] = As[r * ABT_AS_STRIDE + c];
            af[i][1] = As[(r + 8) * ABT_AS_STRIDE + c];
            af[i][2] = As[r * ABT_AS_STRIDE + c + 4];
            af[i][3] = As[(r + 8) * ABT_AS_STRIDE + c + 4];
        }
        #pragma unroll
        for (int j = 0; j < 4; j++) {
            int r = kb + (lane & 3);
            int c = wn + j * 8 + (lane >> 2);
            bf[j][0] = Bs[r * ABT_BS_STRIDE + c];
            bf[j][1] = Bs[(r + 4) * ABT_BS_STRIDE + c];
        }
        #pragma unroll
        for (int i = 0; i < 2; i++)
            #pragma unroll
            for (int j = 0; j < 4; j++)
                mma_tf32(acc[i * 4 + j], af[i], bf[j]);
    }

    #pragma unroll
    for (int i = 0; i < 2; i++) {
        #pragma unroll
        for (int j = 0; j < 4; j++) {
            int r = r0 + wm + i * 16 + (lane >> 2);
            int c = p0 + wn + j * 8 + (lane & 3) * 2;
            float2 v0 = {acc[i * 4 + j][0], acc[i * 4 + j][1]};
            *(float2*)&Cp[((size_t)h * (NBATCH * SEQ) + r) * POS2 + c] = v0;
            float2 v1 = {acc[i * 4 + j][2], acc[i * 4 + j][3]};
            *(float2*)&Cp[((size_t)h * (NBATCH * SEQ) + r + 8) * POS2 + c] = v1;
        }
    }
}

// ================= tensor-core flash attention (v4) ==========================
// 128(q) x 64(k) tiles, 256 threads (8 warps x 16 q-rows), 2 CTAs/SM.
// R4 gather structure (register-resident, high-MLP scattered loads).
#define AQS 68
#define AVS 72

__global__ __launch_bounds__(256, 2) void attn_tc_kernel(float* __restrict__ out) {
    extern __shared__ uint32_t sm[];
    uint32_t* Qs = sm;               // [128][68]
    uint32_t* Ks = Qs + 128 * AQS;   // [64][68]
    uint32_t* Vs = Ks + 64 * AQS;    // [64][72]

    int tid = threadIdx.x;
    int lane = tid & 31, wid = tid >> 5;
    int bh = blockIdx.y;
    int b = bh >> 4, h = bh & 15;
    int q0 = blockIdx.x * 128;

    // load Q tile (tf32): 128 rows x 64 cols
    #pragma unroll
    for (int it = 0; it < 8; it++) {
        int idx = tid + it * 256;
        int row = idx >> 4, col = (idx & 15) * 4;
        float4 v = *(const float4*)&g_Q[(size_t)(b * SEQ + q0 + row) * 1024 + h * 64 + col];
        uint32_t* d = &Qs[row * AQS + col];
        d[0] = f2tf32(v.x); d[1] = f2tf32(v.y); d[2] = f2tf32(v.z); d[3] = f2tf32(v.w);
    }

    int qd = lane & 3, e = qd & 1;
    int srcA = (lane & ~3) | (qd >> 1);
    int srcB = srcA + 2;

    int r0l = wid * 16 + (lane >> 2);
    int row0 = q0 + r0l, row1 = row0 + 8;
    const float* c2p0 = &g_c2p[((size_t)h * (NBATCH * SEQ) + b * SEQ + row0) * POS2];
    const float* c2p1 = &g_c2p[((size_t)h * (NBATCH * SEQ) + b * SEQ + row1) * POS2];
    const float* p2cb = &g_p2c[((size_t)h * (NBATCH * SEQ) + b * SEQ) * POS2];
    const unsigned* pm0 = &g_pmask[(size_t)(b * SEQ + row0) * 32];
    const unsigned* pm1 = &g_pmask[(size_t)(b * SEQ + row1) * 32];

    float m_run0 = -FLT_MAX, m_run1 = -FLT_MAX, l_run0 = 0.0f, l_run1 = 0.0f;
    float O[8][4];
    #pragma unroll
    for (int f = 0; f < 8; f++)
        #pragma unroll
        for (int j = 0; j < 4; j++) O[f][j] = 0.0f;

    const float inv_scale = 0.07216878364870323f; // 1/sqrt(64*3)

    for (int k0 = 0; k0 < SEQ; k0 += 64) {
        __syncthreads();
        // load K,V tiles: 64 rows x 64 cols each; 256 threads -> 4 iterations
        #pragma unroll
        for (int it = 0; it < 4; it++) {
            int idx = tid + it * 256;
            int row = idx >> 4, col = (idx & 15) * 4;
            float4 kv = *(const float4*)&g_K[(size_t)(b * SEQ + k0 + row) * 1024 + h * 64 + col];
            float4 vv = *(const float4*)&g_V[(size_t)(b * SEQ + k0 + row) * 1024 + h * 64 + col];
            uint32_t* dk = &Ks[row * AQS + col];
            dk[0] = f2tf32(kv.x); dk[1] = f2tf32(kv.y); dk[2] = f2tf32(kv.z); dk[3] = f2tf32(kv.w);
            uint32_t* dv = &Vs[row * AVS + col];
            dv[0] = f2tf32(vv.x); dv[1] = f2tf32(vv.y); dv[2] = f2tf32(vv.z); dv[3] = f2tf32(vv.w);
        }
        __syncthreads();

        // ---- S = Q K^T
        float sa[8][4];
        #pragma unroll
        for (int f = 0; f < 8; f++)
            #pragma unroll
            for (int j = 0; j < 4; j++) sa[f][j] = 0.0f;

        #pragma unroll
        for (int ks = 0; ks < 8; ks++) {
            int kb = ks * 8;
            uint32_t a[4];
            a[0] = Qs[r0l * AQS + kb + qd];
            a[1] = Qs[(r0l + 8) * AQS + kb + qd];
            a[2] = Qs[r0l * AQS + kb + 4 + qd];
            a[3] = Qs[(r0l + 8) * AQS + kb + 4 + qd];
            #pragma unroll
            for (int nf = 0; nf < 8; nf++) {
                int n = nf * 8 + (lane >> 2);
                uint32_t bf[2];
                bf[0] = Ks[n * AQS + kb + qd];
                bf[1] = Ks[n * AQS + kb + 4 + qd];
                mma_tf32(sa[nf], a, bf);
            }
        }

        // ---- masks (bit-packed)
        unsigned m0a = pm0[k0 >> 5], m0b = pm0[(k0 >> 5) + 1];
        unsigned m1a = pm1[k0 >> 5], m1b = pm1[(k0 >> 5) + 1];

        // ---- bias + scale + mask (register-resident scattered gathers)
        float s0max = -FLT_MAX, s1max = -FLT_MAX;
        #pragma unroll
        for (int nf = 0; nf < 8; nf++) {
            #pragma unroll
            for (int j = 0; j < 2; j++) {
                int kl = nf * 8 + 2 * qd + j;
                int kg = k0 + kl;
                int d0 = row0 - kg + 1023;
                int2 i0 = __ldg(&g_idx2[d0]);
                int2 i1 = __ldg(&g_idx2[d0 + 8]);
                float v0 = (sa[nf][j] + __ldg(&c2p0[i0.x]) + __ldg(&p2cb[(size_t)kg * POS2 + i0.y])) * inv_scale;
                float v1 = (sa[nf][j + 2] + __ldg(&c2p1[i1.x]) + __ldg(&p2cb[(size_t)kg * POS2 + i1.y])) * inv_scale;
                unsigned w0 = (kl & 32) ? m0b : m0a;
                unsigned w1 = (kl & 32) ? m1b : m1a;
                v0 = ((w0 >> (kl & 31)) & 1u) ? v0 : -FLT_MAX;
                v1 = ((w1 >> (kl & 31)) & 1u) ? v1 : -FLT_MAX;
                sa[nf][j] = v0; sa[nf][j + 2] = v1;
                s0max = fmaxf(s0max, v0); s1max = fmaxf(s1max, v1);
            }
        }

        // ---- online softmax (row over quad)
        s0max = fmaxf(s0max, __shfl_xor_sync(0xffffffffu, s0max, 1));
        s0max = fmaxf(s0max, __shfl_xor_sync(0xffffffffu, s0max, 2));
        s1max = fmaxf(s1max, __shfl_xor_sync(0xffffffffu, s1max, 1));
        s1max = fmaxf(s1max, __shfl_xor_sync(0xffffffffu, s1max, 2));
        float m0n = fmaxf(m_run0, s0max), m1n = fmaxf(m_run1, s1max);
        float a0 = __expf(m_run0 - m0n), a1 = __expf(m_run1 - m1n);
        float psum0 = 0.0f, psum1 = 0.0f;
        #pragma unroll
        for (int nf = 0; nf < 8; nf++) {
            sa[nf][0] = __expf(sa[nf][0] - m0n);
            sa[nf][1] = __expf(sa[nf][1] - m0n);
            sa[nf][2] = __expf(sa[nf][2] - m1n);
            sa[nf][3] = __expf(sa[nf][3] - m1n);
            psum0 += sa[nf][0] + sa[nf][1];
            psum1 += sa[nf][2] + sa[nf][3];
        }
        psum0 += __shfl_xor_sync(0xffffffffu, psum0, 1);
        psum0 += __shfl_xor_sync(0xffffffffu, psum0, 2);
        psum1 += __shfl_xor_sync(0xffffffffu, psum1, 1);
        psum1 += __shfl_xor_sync(0xffffffffu, psum1, 2);
        l_run0 = l_run0 * a0 + psum0;
        l_run1 = l_run1 * a1 + psum1;
        m_run0 = m0n; m_run1 = m1n;
        #pragma unroll
        for (int f = 0; f < 8; f++) {
            O[f][0] *= a0; O[f][1] *= a0; O[f][2] *= a1; O[f][3] *= a1;
        }

        // ---- O += P V : transpose P fragments via quad shfl (no smem)
        #pragma unroll
        for (int ks = 0; ks < 8; ks++) {
            float x0 = __shfl_sync(0xffffffffu, sa[ks][0], srcA);
            float x1 = __shfl_sync(0xffffffffu, sa[ks][1], srcA);
            float x2 = __shfl_sync(0xffffffffu, sa[ks][2], srcA);
            float x3 = __shfl_sync(0xffffffffu, sa[ks][3], srcA);
            float y0 = __shfl_sync(0xffffffffu, sa[ks][0], srcB);
            float y1 = __shfl_sync(0xffffffffu, sa[ks][1], srcB);
            float y2 = __shfl_sync(0xffffffffu, sa[ks][2], srcB);
            float y3 = __shfl_sync(0xffffffffu, sa[ks][3], srcB);
            uint32_t a[4];
            a[0] = f2tf32(e ? x1 : x0);
            a[1] = f2tf32(e ? x3 : x2);
            a[2] = f2tf32(e ? y1 : y0);
            a[3] = f2tf32(e ? y3 : y2);
            int kb = ks * 8;
            #pragma unroll
            for (int nf = 0; nf < 8; nf++) {
                int n = nf * 8 + (lane >> 2);
                uint32_t bf[2];
                bf[0] = Vs[(kb + qd) * AVS + n];
                bf[1] = Vs[(kb + 4 + qd) * AVS + n];
                mma_tf32(O[nf], a, bf);
            }
        }
    }

    // ---- epilogue
    float invl0 = (m_run0 == -FLT_MAX) ? 0.0f : (1.0f / l_run0);
    float invl1 = (m_run1 == -FLT_MAX) ? 0.0f : (1.0f / l_run1);
    #pragma unroll
    for (int nf = 0; nf < 8; nf++) {
        int d = nf * 8 + 2 * qd;
        float2 o0 = {O[nf][0] * invl0, O[nf][1] * invl0};
        *(float2*)&out[(size_t)(b * SEQ + row0) * 1024 + h * 64 + d] = o0;
        float2 o1 = {O[nf][2] * invl1, O[nf][3] * invl1};
        *(float2*)&out[(size_t)(b * SEQ + row1) * 1024 + h * 64 + d] = o1;
    }
}

// ---------------- launch ----------------------------------------------------
extern "C" void kernel_launch(void* const* d_in, const int* in_sizes, int n_in,
                              void* d_out, int out_size) {
    const float* hidden = (const float*)d_in[0];
    const int*   mask   = (const int*)d_in[1];
    const float* rel    = (const float*)d_in[2];
    const float* Wq     = (const float*)d_in[3];
    const float* bq     = (const float*)d_in[4];
    const float* Wk     = (const float*)d_in[5];
    const float* bk     = (const float*)d_in[6];
    const float* Wv     = (const float*)d_in[7];
    const float* bv     = (const float*)d_in[8];
    float* out = (float*)d_out;

    init_tables_kernel<<<8, 256>>>();
    pack_mask_kernel<<<NBATCH * SEQ * SEQ / 256, 256>>>(mask);

    int smem_qkv = (2 * QKV_ABUF + 2 * QKV_BBUF) * (int)sizeof(uint32_t);
    cudaFuncSetAttribute(gemm_proj_tf32, cudaFuncAttributeMaxDynamicSharedMemorySize, smem_qkv);
    gemm_proj_tf32<<<dim3(8, 20, 3), 256, smem_qkv>>>(
        hidden, rel, Wq, Wk, Wv, bq, bk, bv);

    int smem_abt = (128 * ABT_AS_STRIDE + 64 * ABT_BS_STRIDE) * (int)sizeof(uint32_t);
    cudaFuncSetAttribute(gemm_abT_tf32, cudaFuncAttributeMaxDynamicSharedMemorySize, smem_abt);
    gemm_abT_tf32<<<dim3(8, 16, 32), 256, smem_abt>>>();

    int smem_attn = ((128 + 64) * AQS + 64 * AVS) * (int)sizeof(uint32_t);
    cudaFuncSetAttribute(attn_tc_kernel, cudaFuncAttributeMaxDynamicSharedMemorySize, smem_attn);
    attn_tc_kernel<<<dim3(SEQ / 128, NBATCH * NHEAD), 256, smem_attn>>>(out);
}

// round 7
// speedup vs baseline: 1.7088x; 1.0589x over previous
#include <cuda_runtime.h>
#include <cuda_fp16.h>
#include <math.h>
#include <float.h>
#include <stdint.h>

#define SEQ    1024
#define DMODEL 1024
#define NHEAD  16
#define DHEAD  64
#define NBATCH 2
#define POS2   512

// ---------------- scratch ----------------------------------------------------
__device__ float g_Q[NBATCH * SEQ * DMODEL];
__device__ float g_K[NBATCH * SEQ * DMODEL];
__device__ float g_V[NBATCH * SEQ * DMODEL];
__device__ float g_PQ[POS2 * DMODEL];
__device__ float g_PK[POS2 * DMODEL];
__device__ __half g_c2p[NHEAD * NBATCH * SEQ * POS2];   // [h][g][bucket] fp16
__device__ __half g_p2c[NHEAD * NBATCH * SEQ * POS2];   // [h][g][bucket] fp16
__device__ int2  g_idx2[2047];                          // (idxC, idxP)
__device__ unsigned g_pmask[NBATCH * SEQ * (SEQ / 32)];

// ---------------- helpers ----------------------------------------------------
__device__ __forceinline__ uint32_t f2tf32(float x) {
    uint32_t r;
    asm("cvt.rna.tf32.f32 %0, %1;" : "=r"(r) : "f"(x));
    return r;
}
__device__ __forceinline__ void mma_tf32(float c[4], const uint32_t a[4], const uint32_t b[2]) {
    asm volatile(
        "mma.sync.aligned.m16n8k8.row.col.f32.tf32.tf32.f32 "
        "{%0,%1,%2,%3}, {%4,%5,%6,%7}, {%8,%9}, {%0,%1,%2,%3};"
        : "+f"(c[0]), "+f"(c[1]), "+f"(c[2]), "+f"(c[3])
        : "r"(a[0]), "r"(a[1]), "r"(a[2]), "r"(a[3]), "r"(b[0]), "r"(b[1]));
}

// ---------------- log-bucket tables ------------------------------------------
__device__ __forceinline__ int log_bucket(int rel) {
    const int mid = 128;
    float absp;
    if (rel < mid && rel > -mid) absp = (float)(mid - 1);
    else absp = fabsf((float)rel);
    if (absp <= (float)mid) return rel;
    float lp = ceilf(logf(absp / 128.0f) / 1.3843393291f * 127.0f) + 128.0f;
    float sgn = (rel > 0) ? 1.0f : ((rel < 0) ? -1.0f : 0.0f);
    return (int)(lp * sgn);
}
__global__ void init_tables_kernel() {
    int t = blockIdx.x * blockDim.x + threadIdx.x;
    if (t < 2047) {
        int delta = t - 1023;
        int bC = log_bucket(delta);
        int bP = log_bucket(-delta);
        int2 v;
        v.x = min(max(bC + 256, 0), 511);
        v.y = min(max(-bP + 256, 0), 511);
        g_idx2[t] = v;
    }
}

// ---------------- mask bit-pack ----------------------------------------------
__global__ void pack_mask_kernel(const int* __restrict__ mask) {
    int idx = blockIdx.x * 256 + threadIdx.x;
    int v = mask[idx];
    unsigned bal = __ballot_sync(0xffffffffu, v != 0);
    if ((threadIdx.x & 31) == 0) g_pmask[idx >> 5] = bal;
}

// ================= TF32 GEMM: projections (QKV + positional merged) ==========
#define QKV_AS_STRIDE 36
#define QKV_BS_STRIDE 136
#define QKV_ABUF (128 * QKV_AS_STRIDE)
#define QKV_BBUF (32 * QKV_BS_STRIDE)

__global__ __launch_bounds__(256) void gemm_proj_tf32(
    const float* __restrict__ hidden, const float* __restrict__ rel,
    const float* __restrict__ Wq, const float* __restrict__ Wk, const float* __restrict__ Wv,
    const float* __restrict__ bq, const float* __restrict__ bk, const float* __restrict__ bv) {

    int z = blockIdx.z;
    int y = blockIdx.y;
    const float* A;
    float* C;
    int m0;
    if (y < 16) {
        A = hidden; m0 = y * 128;
        C = (z == 0) ? g_Q : (z == 1) ? g_K : g_V;
    } else {
        if (z == 2) return;
        A = rel; m0 = (y - 16) * 128;
        C = (z == 0) ? g_PQ : g_PK;
    }
    const float* W = (z == 0) ? Wq : (z == 1) ? Wk : Wv;
    const float* bias = (z == 0) ? bq : (z == 1) ? bk : bv;

    extern __shared__ uint32_t smu[];
    uint32_t* As = smu;
    uint32_t* Bs = smu + 2 * QKV_ABUF;

    int tid = threadIdx.x;
    int lane = tid & 31, wid = tid >> 5;
    int wm = (wid >> 2) * 64, wn = (wid & 3) * 32;
    int n0 = blockIdx.x * 128;

    int arow = tid >> 3, acol = (tid & 7) * 4;
    int brow = tid >> 5, bcol = (tid & 31) * 4;

    float4 ra[4], rb[4];
    float acc[16][4];
    #pragma unroll
    for (int t = 0; t < 16; t++)
        #pragma unroll
        for (int j = 0; j < 4; j++) acc[t][j] = 0.0f;

    #pragma unroll
    for (int p = 0; p < 4; p++) {
        ra[p] = *(const float4*)&A[(size_t)(m0 + arow + p * 32) * 1024 + acol];
        rb[p] = *(const float4*)&W[(size_t)(brow + p * 8) * 1024 + n0 + bcol];
    }
    #pragma unroll
    for (int p = 0; p < 4; p++) {
        uint32_t* d = &As[(arow + p * 32) * QKV_AS_STRIDE + acol];
        d[0] = f2tf32(ra[p].x); d[1] = f2tf32(ra[p].y); d[2] = f2tf32(ra[p].z); d[3] = f2tf32(ra[p].w);
        uint32_t* e = &Bs[(brow + p * 8) * QKV_BS_STRIDE + bcol];
        e[0] = f2tf32(rb[p].x); e[1] = f2tf32(rb[p].y); e[2] = f2tf32(rb[p].z); e[3] = f2tf32(rb[p].w);
    }
    __syncthreads();

    int buf = 0;
    for (int kk = 32; kk <= 1024; kk += 32) {
        if (kk < 1024) {
            #pragma unroll
            for (int p = 0; p < 4; p++) {
                ra[p] = *(const float4*)&A[(size_t)(m0 + arow + p * 32) * 1024 + kk + acol];
                rb[p] = *(const float4*)&W[(size_t)(kk + brow + p * 8) * 1024 + n0 + bcol];
            }
        }
        const uint32_t* Ab = &As[buf * QKV_ABUF];
        const uint32_t* Bb = &Bs[buf * QKV_BBUF];
        #pragma unroll
        for (int ks = 0; ks < 4; ks++) {
            int kb = ks * 8;
            uint32_t af[4][4], bf[4][2];
            #pragma unroll
            for (int i = 0; i < 4; i++) {
                int r = wm + i * 16 + (lane >> 2);
                int c = kb + (lane & 3);
                af[i][0] = Ab[r * QKV_AS_STRIDE + c];
                af[i][1] = Ab[(r + 8) * QKV_AS_STRIDE + c];
                af[i][2] = Ab[r * QKV_AS_STRIDE + c + 4];
                af[i][3] = Ab[(r + 8) * QKV_AS_STRIDE + c + 4];
            }
            #pragma unroll
            for (int j = 0; j < 4; j++) {
                int r = kb + (lane & 3);
                int c = wn + j * 8 + (lane >> 2);
                bf[j][0] = Bb[r * QKV_BS_STRIDE + c];
                bf[j][1] = Bb[(r + 4) * QKV_BS_STRIDE + c];
            }
            #pragma unroll
            for (int i = 0; i < 4; i++)
                #pragma unroll
                for (int j = 0; j < 4; j++)
                    mma_tf32(acc[i * 4 + j], af[i], bf[j]);
        }
        __syncthreads();
        if (kk < 1024) {
            buf ^= 1;
            #pragma unroll
            for (int p = 0; p < 4; p++) {
                uint32_t* d = &As[buf * QKV_ABUF + (arow + p * 32) * QKV_AS_STRIDE + acol];
                d[0] = f2tf32(ra[p].x); d[1] = f2tf32(ra[p].y); d[2] = f2tf32(ra[p].z); d[3] = f2tf32(ra[p].w);
                uint32_t* e = &Bs[buf * QKV_BBUF + (brow + p * 8) * QKV_BS_STRIDE + bcol];
                e[0] = f2tf32(rb[p].x); e[1] = f2tf32(rb[p].y); e[2] = f2tf32(rb[p].z); e[3] = f2tf32(rb[p].w);
            }
            __syncthreads();
        }
    }

    #pragma unroll
    for (int i = 0; i < 4; i++) {
        #pragma unroll
        for (int j = 0; j < 4; j++) {
            int r = m0 + wm + i * 16 + (lane >> 2);
            int c = n0 + wn + j * 8 + (lane & 3) * 2;
            float bx = bias[c], by = bias[c + 1];
            float2 v0 = {acc[i * 4 + j][0] + bx, acc[i * 4 + j][1] + by};
            *(float2*)&C[(size_t)r * 1024 + c] = v0;
            float2 v1 = {acc[i * 4 + j][2] + bx, acc[i * 4 + j][3] + by};
            *(float2*)&C[(size_t)(r + 8) * 1024 + c] = v1;
        }
    }
}

// ============ TF32 per-head A@B^T (c2p_att / p2c_att), fp16 g-major output ===
// tile 128(g) x 128(p), 256 threads (8 warps: 4m x 2n), K=64 single-shot.
#define ABT_AS_STRIDE 68
#define ABT_BS_STRIDE 136

__global__ __launch_bounds__(256) void gemm_abT_tf32() {
    int z = blockIdx.z;
    int h = z & 15;
    const float* Ap = (z < 16) ? g_Q : g_K;
    const float* Bp = (z < 16) ? g_PK : g_PQ;
    __half* Cp = (z < 16) ? g_c2p : g_p2c;

    extern __shared__ uint32_t smu[];
    uint32_t* As = smu;                       // [128][68]   (g x d)
    uint32_t* Bs = smu + 128 * ABT_AS_STRIDE; // [64][136]   ([d][p]), p=128

    int tid = threadIdx.x;
    int lane = tid & 31, wid = tid >> 5;
    int wm = (wid >> 1) * 32, wn = (wid & 1) * 64;
    int r0 = blockIdx.y * 128, p0 = blockIdx.x * 128;

    // load A tile [128 g][64 d]
    {
        int row = tid >> 4, col = (tid & 15) * 4;
        #pragma unroll
        for (int p = 0; p < 8; p++) {
            float4 v = *(const float4*)&Ap[(size_t)(r0 + row + p * 16) * 1024 + h * 64 + col];
            uint32_t* d = &As[(row + p * 16) * ABT_AS_STRIDE + col];
            d[0] = f2tf32(v.x); d[1] = f2tf32(v.y); d[2] = f2tf32(v.z); d[3] = f2tf32(v.w);
        }
    }
    // load B tile transposed: Bs[d][p], p = 128 rows of Bp
    {
        int pp = tid & 127, d4 = (tid >> 7) * 4;   // d4 in {0,4}
        #pragma unroll
        for (int ps = 0; ps < 8; ps++) {
            int d = d4 + ps * 8;
            float4 v = *(const float4*)&Bp[(size_t)(p0 + pp) * 1024 + h * 64 + d];
            Bs[(d + 0) * ABT_BS_STRIDE + pp] = f2tf32(v.x);
            Bs[(d + 1) * ABT_BS_STRIDE + pp] = f2tf32(v.y);
            Bs[(d + 2) * ABT_BS_STRIDE + pp] = f2tf32(v.z);
            Bs[(d + 3) * ABT_BS_STRIDE + pp] = f2tf32(v.w);
        }
    }
    __syncthreads();

    float acc[16][4];
    #pragma unroll
    for (int t = 0; t < 16; t++)
        #pragma unroll
        for (int j = 0; j < 4; j++) acc[t][j] = 0.0f;

    #pragma unroll
    for (int ks = 0; ks < 8; ks++) {
        int kb = ks * 8;
        uint32_t af[2][4], bf[8][2];
        #pragma unroll
        for (int i = 0; i < 2; i++) {
            int r = wm + i * 16 + (lane >> 2);
            int c = kb + (lane & 3);
            af[i][0] = As[r * ABT_AS_STRIDE + c];
            af[i][1] = As[(r + 8) * ABT_AS_STRIDE + c];
            af[i][2] = As[r * ABT_AS_STRIDE + c + 4];
            af[i][3] = As[(r + 8) * ABT_AS_STRIDE + c + 4];
        }
        #pragma unroll
        for (int j = 0; j < 8; j++) {
            int r = kb + (lane & 3);
            int c = wn + j * 8 + (lane >> 2);
            bf[j][0] = Bs[r * ABT_BS_STRIDE + c];
            bf[j][1] = Bs[(r + 4) * ABT_BS_STRIDE + c];
        }
        #pragma unroll
        for (int i = 0; i < 2; i++)
            #pragma unroll
            for (int j = 0; j < 8; j++)
                mma_tf32(acc[i * 8 + j], af[i], bf[j]);
    }

    #pragma unroll
    for (int i = 0; i < 2; i++) {
        #pragma unroll
        for (int j = 0; j < 8; j++) {
            int r = r0 + wm + i * 16 + (lane >> 2);
            int c = p0 + wn + j * 8 + (lane & 3) * 2;
            __half2 v0 = __floats2half2_rn(acc[i * 8 + j][0], acc[i * 8 + j][1]);
            *(__half2*)&Cp[((size_t)h * (NBATCH * SEQ) + r) * POS2 + c] = v0;
            __half2 v1 = __floats2half2_rn(acc[i * 8 + j][2], acc[i * 8 + j][3]);
            *(__half2*)&Cp[((size_t)h * (NBATCH * SEQ) + r + 8) * POS2 + c] = v1;
        }
    }
}

// ================= tensor-core flash attention (v4, fp16 gathers) ============
#define AQS 68
#define AVS 72

__global__ __launch_bounds__(256, 2) void attn_tc_kernel(float* __restrict__ out) {
    extern __shared__ uint32_t sm[];
    uint32_t* Qs = sm;               // [128][68]
    uint32_t* Ks = Qs + 128 * AQS;   // [64][68]
    uint32_t* Vs = Ks + 64 * AQS;    // [64][72]

    int tid = threadIdx.x;
    int lane = tid & 31, wid = tid >> 5;
    int bh = blockIdx.y;
    int b = bh >> 4, h = bh & 15;
    int q0 = blockIdx.x * 128;

    // load Q tile (tf32): 128 rows x 64 cols
    #pragma unroll
    for (int it = 0; it < 8; it++) {
        int idx = tid + it * 256;
        int row = idx >> 4, col = (idx & 15) * 4;
        float4 v = *(const float4*)&g_Q[(size_t)(b * SEQ + q0 + row) * 1024 + h * 64 + col];
        uint32_t* d = &Qs[row * AQS + col];
        d[0] = f2tf32(v.x); d[1] = f2tf32(v.y); d[2] = f2tf32(v.z); d[3] = f2tf32(v.w);
    }

    int qd = lane & 3, e = qd & 1;
    int srcA = (lane & ~3) | (qd >> 1);
    int srcB = srcA + 2;

    int r0l = wid * 16 + (lane >> 2);
    int row0 = q0 + r0l, row1 = row0 + 8;
    const __half* c2p0 = &g_c2p[((size_t)h * (NBATCH * SEQ) + b * SEQ + row0) * POS2];
    const __half* c2p1 = &g_c2p[((size_t)h * (NBATCH * SEQ) + b * SEQ + row1) * POS2];
    const __half* p2cb = &g_p2c[((size_t)h * (NBATCH * SEQ) + b * SEQ) * POS2];
    const unsigned* pm0 = &g_pmask[(size_t)(b * SEQ + row0) * 32];
    const unsigned* pm1 = &g_pmask[(size_t)(b * SEQ + row1) * 32];

    float m_run0 = -FLT_MAX, m_run1 = -FLT_MAX, l_run0 = 0.0f, l_run1 = 0.0f;
    float O[8][4];
    #pragma unroll
    for (int f = 0; f < 8; f++)
        #pragma unroll
        for (int j = 0; j < 4; j++) O[f][j] = 0.0f;

    const float inv_scale = 0.07216878364870323f; // 1/sqrt(64*3)

    for (int k0 = 0; k0 < SEQ; k0 += 64) {
        __syncthreads();
        #pragma unroll
        for (int it = 0; it < 4; it++) {
            int idx = tid + it * 256;
            int row = idx >> 4, col = (idx & 15) * 4;
            float4 kv = *(const float4*)&g_K[(size_t)(b * SEQ + k0 + row) * 1024 + h * 64 + col];
            float4 vv = *(const float4*)&g_V[(size_t)(b * SEQ + k0 + row) * 1024 + h * 64 + col];
            uint32_t* dk = &Ks[row * AQS + col];
            dk[0] = f2tf32(kv.x); dk[1] = f2tf32(kv.y); dk[2] = f2tf32(kv.z); dk[3] = f2tf32(kv.w);
            uint32_t* dv = &Vs[row * AVS + col];
            dv[0] = f2tf32(vv.x); dv[1] = f2tf32(vv.y); dv[2] = f2tf32(vv.z); dv[3] = f2tf32(vv.w);
        }
        __syncthreads();

        // ---- S = Q K^T
        float sa[8][4];
        #pragma unroll
        for (int f = 0; f < 8; f++)
            #pragma unroll
            for (int j = 0; j < 4; j++) sa[f][j] = 0.0f;

        #pragma unroll
        for (int ks = 0; ks < 8; ks++) {
            int kb = ks * 8;
            uint32_t a[4];
            a[0] = Qs[r0l * AQS + kb + qd];
            a[1] = Qs[(r0l + 8) * AQS + kb + qd];
            a[2] = Qs[r0l * AQS + kb + 4 + qd];
            a[3] = Qs[(r0l + 8) * AQS + kb + 4 + qd];
            #pragma unroll
            for (int nf = 0; nf < 8; nf++) {
                int n = nf * 8 + (lane >> 2);
                uint32_t bf[2];
                bf[0] = Ks[n * AQS + kb + qd];
                bf[1] = Ks[n * AQS + kb + 4 + qd];
                mma_tf32(sa[nf], a, bf);
            }
        }

        // ---- masks (bit-packed)
        unsigned m0a = pm0[k0 >> 5], m0b = pm0[(k0 >> 5) + 1];
        unsigned m1a = pm1[k0 >> 5], m1b = pm1[(k0 >> 5) + 1];

        // ---- bias + scale + mask (register-resident scattered fp16 gathers)
        float s0max = -FLT_MAX, s1max = -FLT_MAX;
        #pragma unroll
        for (int nf = 0; nf < 8; nf++) {
            #pragma unroll
            for (int j = 0; j < 2; j++) {
                int kl = nf * 8 + 2 * qd + j;
                int kg = k0 + kl;
                int d0 = row0 - kg + 1023;
                int2 i0 = __ldg(&g_idx2[d0]);
                int2 i1 = __ldg(&g_idx2[d0 + 8]);
                float b0 = __half2float(__ldg(&c2p0[i0.x])) + __half2float(__ldg(&p2cb[(size_t)kg * POS2 + i0.y]));
                float b1 = __half2float(__ldg(&c2p1[i1.x])) + __half2float(__ldg(&p2cb[(size_t)kg * POS2 + i1.y]));
                float v0 = (sa[nf][j] + b0) * inv_scale;
                float v1 = (sa[nf][j + 2] + b1) * inv_scale;
                unsigned w0 = (kl & 32) ? m0b : m0a;
                unsigned w1 = (kl & 32) ? m1b : m1a;
                v0 = ((w0 >> (kl & 31)) & 1u) ? v0 : -FLT_MAX;
                v1 = ((w1 >> (kl & 31)) & 1u) ? v1 : -FLT_MAX;
                sa[nf][j] = v0; sa[nf][j + 2] = v1;
                s0max = fmaxf(s0max, v0); s1max = fmaxf(s1max, v1);
            }
        }

        // ---- online softmax (row over quad)
        s0max = fmaxf(s0max, __shfl_xor_sync(0xffffffffu, s0max, 1));
        s0max = fmaxf(s0max, __shfl_xor_sync(0xffffffffu, s0max, 2));
        s1max = fmaxf(s1max, __shfl_xor_sync(0xffffffffu, s1max, 1));
        s1max = fmaxf(s1max, __shfl_xor_sync(0xffffffffu, s1max, 2));
        float m0n = fmaxf(m_run0, s0max), m1n = fmaxf(m_run1, s1max);
        float a0 = __expf(m_run0 - m0n), a1 = __expf(m_run1 - m1n);
        float psum0 = 0.0f, psum1 = 0.0f;
        #pragma unroll
        for (int nf = 0; nf < 8; nf++) {
            sa[nf][0] = __expf(sa[nf][0] - m0n);
            sa[nf][1] = __expf(sa[nf][1] - m0n);
            sa[nf][2] = __expf(sa[nf][2] - m1n);
            sa[nf][3] = __expf(sa[nf][3] - m1n);
            psum0 += sa[nf][0] + sa[nf][1];
            psum1 += sa[nf][2] + sa[nf][3];
        }
        psum0 += __shfl_xor_sync(0xffffffffu, psum0, 1);
        psum0 += __shfl_xor_sync(0xffffffffu, psum0, 2);
        psum1 += __shfl_xor_sync(0xffffffffu, psum1, 1);
        psum1 += __shfl_xor_sync(0xffffffffu, psum1, 2);
        l_run0 = l_run0 * a0 + psum0;
        l_run1 = l_run1 * a1 + psum1;
        m_run0 = m0n; m_run1 = m1n;
        #pragma unroll
        for (int f = 0; f < 8; f++) {
            O[f][0] *= a0; O[f][1] *= a0; O[f][2] *= a1; O[f][3] *= a1;
        }

        // ---- O += P V : transpose P fragments via quad shfl (no smem)
        #pragma unroll
        for (int ks = 0; ks < 8; ks++) {
            float x0 = __shfl_sync(0xffffffffu, sa[ks][0], srcA);
            float x1 = __shfl_sync(0xffffffffu, sa[ks][1], srcA);
            float x2 = __shfl_sync(0xffffffffu, sa[ks][2], srcA);
            float x3 = __shfl_sync(0xffffffffu, sa[ks][3], srcA);
            float y0 = __shfl_sync(0xffffffffu, sa[ks][0], srcB);
            float y1 = __shfl_sync(0xffffffffu, sa[ks][1], srcB);
            float y2 = __shfl_sync(0xffffffffu, sa[ks][2], srcB);
            float y3 = __shfl_sync(0xffffffffu, sa[ks][3], srcB);
            uint32_t a[4];
            a[0] = f2tf32(e ? x1 : x0);
            a[1] = f2tf32(e ? x3 : x2);
            a[2] = f2tf32(e ? y1 : y0);
            a[3] = f2tf32(e ? y3 : y2);
            int kb = ks * 8;
            #pragma unroll
            for (int nf = 0; nf < 8; nf++) {
                int n = nf * 8 + (lane >> 2);
                uint32_t bf[2];
                bf[0] = Vs[(kb + qd) * AVS + n];
                bf[1] = Vs[(kb + 4 + qd) * AVS + n];
                mma_tf32(O[nf], a, bf);
            }
        }
    }

    // ---- epilogue
    float invl0 = (m_run0 == -FLT_MAX) ? 0.0f : (1.0f / l_run0);
    float invl1 = (m_run1 == -FLT_MAX) ? 0.0f : (1.0f / l_run1);
    #pragma unroll
    for (int nf = 0; nf < 8; nf++) {
        int d = nf * 8 + 2 * qd;
        float2 o0 = {O[nf][0] * invl0, O[nf][1] * invl0};
        *(float2*)&out[(size_t)(b * SEQ + row0) * 1024 + h * 64 + d] = o0;
        float2 o1 = {O[nf][2] * invl1, O[nf][3] * invl1};
        *(float2*)&out[(size_t)(b * SEQ + row1) * 1024 + h * 64 + d] = o1;
    }
}

// ---------------- launch ----------------------------------------------------
extern "C" void kernel_launch(void* const* d_in, const int* in_sizes, int n_in,
                              void* d_out, int out_size) {
    const float* hidden = (const float*)d_in[0];
    const int*   mask   = (const int*)d_in[1];
    const float* rel    = (const float*)d_in[2];
    const float* Wq     = (const float*)d_in[3];
    const float* bq     = (const float*)d_in[4];
    const float* Wk     = (const float*)d_in[5];
    const float* bk     = (const float*)d_in[6];
    const float* Wv     = (const float*)d_in[7];
    const float* bv     = (const float*)d_in[8];
    float* out = (float*)d_out;

    init_tables_kernel<<<8, 256>>>();
    pack_mask_kernel<<<NBATCH * SEQ * SEQ / 256, 256>>>(mask);

    int smem_qkv = (2 * QKV_ABUF + 2 * QKV_BBUF) * (int)sizeof(uint32_t);
    cudaFuncSetAttribute(gemm_proj_tf32, cudaFuncAttributeMaxDynamicSharedMemorySize, smem_qkv);
    gemm_proj_tf32<<<dim3(8, 20, 3), 256, smem_qkv>>>(
        hidden, rel, Wq, Wk, Wv, bq, bk, bv);

    int smem_abt = (128 * ABT_AS_STRIDE + 64 * ABT_BS_STRIDE) * (int)sizeof(uint32_t);
    cudaFuncSetAttribute(gemm_abT_tf32, cudaFuncAttributeMaxDynamicSharedMemorySize, smem_abt);
    gemm_abT_tf32<<<dim3(POS2 / 128, 16, 32), 256, smem_abt>>>();

    int smem_attn = ((128 + 64) * AQS + 64 * AVS) * (int)sizeof(uint32_t);
    cudaFuncSetAttribute(attn_tc_kernel, cudaFuncAttributeMaxDynamicSharedMemorySize, smem_attn);
    attn_tc_kernel<<<dim3(SEQ / 128, NBATCH * NHEAD), 256, smem_attn>>>(out);
}

// round 8
// speedup vs baseline: 2.1527x; 1.2597x over previous
#include <cuda_runtime.h>
#include <cuda_fp16.h>
#include <math.h>
#include <float.h>
#include <stdint.h>

#define SEQ    1024
#define DMODEL 1024
#define NHEAD  16
#define DHEAD  64
#define NBATCH 2
#define POS2   512

// ---------------- scratch ----------------------------------------------------
__device__ __half g_Q[NBATCH * SEQ * DMODEL];            // [g][ch] fp16
__device__ __half g_K[NBATCH * SEQ * DMODEL];            // [g][ch] fp16
__device__ __half g_VT[NBATCH * DMODEL * SEQ];           // [b*1024+ch][s] fp16 (transposed)
__device__ __half g_PQ[POS2 * DMODEL];
__device__ __half g_PK[POS2 * DMODEL];
__device__ __half g_c2p[NHEAD * NBATCH * SEQ * POS2];    // [h][g][bucket]
__device__ __half g_p2c[NHEAD * NBATCH * SEQ * POS2];    // [h][g][bucket]
__device__ int2  g_idx2[2047];                           // (idxC, idxP)
__device__ unsigned g_pmask[NBATCH * SEQ * (SEQ / 32)];

// ---------------- helpers ----------------------------------------------------
__device__ __forceinline__ uint32_t f2tf32(float x) {
    uint32_t r;
    asm("cvt.rna.tf32.f32 %0, %1;" : "=r"(r) : "f"(x));
    return r;
}
__device__ __forceinline__ void mma_tf32(float c[4], const uint32_t a[4], const uint32_t b[2]) {
    asm volatile(
        "mma.sync.aligned.m16n8k8.row.col.f32.tf32.tf32.f32 "
        "{%0,%1,%2,%3}, {%4,%5,%6,%7}, {%8,%9}, {%0,%1,%2,%3};"
        : "+f"(c[0]), "+f"(c[1]), "+f"(c[2]), "+f"(c[3])
        : "r"(a[0]), "r"(a[1]), "r"(a[2]), "r"(a[3]), "r"(b[0]), "r"(b[1]));
}
__device__ __forceinline__ void mma_f16(float c[4], const uint32_t a[4], const uint32_t b[2]) {
    asm volatile(
        "mma.sync.aligned.m16n8k16.row.col.f32.f16.f16.f32 "
        "{%0,%1,%2,%3}, {%4,%5,%6,%7}, {%8,%9}, {%0,%1,%2,%3};"
        : "+f"(c[0]), "+f"(c[1]), "+f"(c[2]), "+f"(c[3])
        : "r"(a[0]), "r"(a[1]), "r"(a[2]), "r"(a[3]), "r"(b[0]), "r"(b[1]));
}
__device__ __forceinline__ uint32_t packh2(float lo, float hi) {
    __half2 h = __floats2half2_rn(lo, hi);
    return *(uint32_t*)&h;
}

// ---------------- log-bucket tables ------------------------------------------
__device__ __forceinline__ int log_bucket(int rel) {
    const int mid = 128;
    float absp;
    if (rel < mid && rel > -mid) absp = (float)(mid - 1);
    else absp = fabsf((float)rel);
    if (absp <= (float)mid) return rel;
    float lp = ceilf(logf(absp / 128.0f) / 1.3843393291f * 127.0f) + 128.0f;
    float sgn = (rel > 0) ? 1.0f : ((rel < 0) ? -1.0f : 0.0f);
    return (int)(lp * sgn);
}
__global__ void init_tables_kernel() {
    int t = blockIdx.x * blockDim.x + threadIdx.x;
    if (t < 2047) {
        int delta = t - 1023;
        int bC = log_bucket(delta);
        int bP = log_bucket(-delta);
        int2 v;
        v.x = min(max(bC + 256, 0), 511);
        v.y = min(max(-bP + 256, 0), 511);
        g_idx2[t] = v;
    }
}

// ---------------- mask bit-pack ----------------------------------------------
__global__ void pack_mask_kernel(const int* __restrict__ mask) {
    int idx = blockIdx.x * 256 + threadIdx.x;
    int v = mask[idx];
    unsigned bal = __ballot_sync(0xffffffffu, v != 0);
    if ((threadIdx.x & 31) == 0) g_pmask[idx >> 5] = bal;
}

// ================= TF32 GEMM: projections -> fp16 outputs ====================
#define QKV_AS_STRIDE 36
#define QKV_BS_STRIDE 136
#define QKV_ABUF (128 * QKV_AS_STRIDE)
#define QKV_BBUF (32 * QKV_BS_STRIDE)

__global__ __launch_bounds__(256) void gemm_proj_tf32(
    const float* __restrict__ hidden, const float* __restrict__ rel,
    const float* __restrict__ Wq, const float* __restrict__ Wk, const float* __restrict__ Wv,
    const float* __restrict__ bq, const float* __restrict__ bk, const float* __restrict__ bv) {

    int z = blockIdx.z;
    int y = blockIdx.y;
    const float* A;
    __half* Ch = nullptr;
    bool isV = false;
    int m0;
    if (y < 16) {
        A = hidden; m0 = y * 128;
        if (z == 0) Ch = g_Q; else if (z == 1) Ch = g_K; else isV = true;
    } else {
        if (z == 2) return;
        A = rel; m0 = (y - 16) * 128;
        Ch = (z == 0) ? g_PQ : g_PK;
    }
    const float* W = (z == 0) ? Wq : (z == 1) ? Wk : Wv;
    const float* bias = (z == 0) ? bq : (z == 1) ? bk : bv;

    extern __shared__ uint32_t smu[];
    uint32_t* As = smu;
    uint32_t* Bs = smu + 2 * QKV_ABUF;

    int tid = threadIdx.x;
    int lane = tid & 31, wid = tid >> 5;
    int wm = (wid >> 2) * 64, wn = (wid & 3) * 32;
    int n0 = blockIdx.x * 128;

    int arow = tid >> 3, acol = (tid & 7) * 4;
    int brow = tid >> 5, bcol = (tid & 31) * 4;

    float4 ra[4], rb[4];
    float acc[16][4];
    #pragma unroll
    for (int t = 0; t < 16; t++)
        #pragma unroll
        for (int j = 0; j < 4; j++) acc[t][j] = 0.0f;

    #pragma unroll
    for (int p = 0; p < 4; p++) {
        ra[p] = *(const float4*)&A[(size_t)(m0 + arow + p * 32) * 1024 + acol];
        rb[p] = *(const float4*)&W[(size_t)(brow + p * 8) * 1024 + n0 + bcol];
    }
    #pragma unroll
    for (int p = 0; p < 4; p++) {
        uint32_t* d = &As[(arow + p * 32) * QKV_AS_STRIDE + acol];
        d[0] = f2tf32(ra[p].x); d[1] = f2tf32(ra[p].y); d[2] = f2tf32(ra[p].z); d[3] = f2tf32(ra[p].w);
        uint32_t* e = &Bs[(brow + p * 8) * QKV_BS_STRIDE + bcol];
        e[0] = f2tf32(rb[p].x); e[1] = f2tf32(rb[p].y); e[2] = f2tf32(rb[p].z); e[3] = f2tf32(rb[p].w);
    }
    __syncthreads();

    int buf = 0;
    for (int kk = 32; kk <= 1024; kk += 32) {
        if (kk < 1024) {
            #pragma unroll
            for (int p = 0; p < 4; p++) {
                ra[p] = *(const float4*)&A[(size_t)(m0 + arow + p * 32) * 1024 + kk + acol];
                rb[p] = *(const float4*)&W[(size_t)(kk + brow + p * 8) * 1024 + n0 + bcol];
            }
        }
        const uint32_t* Ab = &As[buf * QKV_ABUF];
        const uint32_t* Bb = &Bs[buf * QKV_BBUF];
        #pragma unroll
        for (int ks = 0; ks < 4; ks++) {
            int kb = ks * 8;
            uint32_t af[4][4], bf[4][2];
            #pragma unroll
            for (int i = 0; i < 4; i++) {
                int r = wm + i * 16 + (lane >> 2);
                int c = kb + (lane & 3);
                af[i][0] = Ab[r * QKV_AS_STRIDE + c];
                af[i][1] = Ab[(r + 8) * QKV_AS_STRIDE + c];
                af[i][2] = Ab[r * QKV_AS_STRIDE + c + 4];
                af[i][3] = Ab[(r + 8) * QKV_AS_STRIDE + c + 4];
            }
            #pragma unroll
            for (int j = 0; j < 4; j++) {
                int r = kb + (lane & 3);
                int c = wn + j * 8 + (lane >> 2);
                bf[j][0] = Bb[r * QKV_BS_STRIDE + c];
                bf[j][1] = Bb[(r + 4) * QKV_BS_STRIDE + c];
            }
            #pragma unroll
            for (int i = 0; i < 4; i++)
                #pragma unroll
                for (int j = 0; j < 4; j++)
                    mma_tf32(acc[i * 4 + j], af[i], bf[j]);
        }
        __syncthreads();
        if (kk < 1024) {
            buf ^= 1;
            #pragma unroll
            for (int p = 0; p < 4; p++) {
                uint32_t* d = &As[buf * QKV_ABUF + (arow + p * 32) * QKV_AS_STRIDE + acol];
                d[0] = f2tf32(ra[p].x); d[1] = f2tf32(ra[p].y); d[2] = f2tf32(ra[p].z); d[3] = f2tf32(ra[p].w);
                uint32_t* e = &Bs[buf * QKV_BBUF + (brow + p * 8) * QKV_BS_STRIDE + bcol];
                e[0] = f2tf32(rb[p].x); e[1] = f2tf32(rb[p].y); e[2] = f2tf32(rb[p].z); e[3] = f2tf32(rb[p].w);
            }
            __syncthreads();
        }
    }

    #pragma unroll
    for (int i = 0; i < 4; i++) {
        #pragma unroll
        for (int j = 0; j < 4; j++) {
            int r = m0 + wm + i * 16 + (lane >> 2);
            int c = n0 + wn + j * 8 + (lane & 3) * 2;
            float bx = bias[c], by = bias[c + 1];
            float v00 = acc[i * 4 + j][0] + bx, v01 = acc[i * 4 + j][1] + by;
            float v10 = acc[i * 4 + j][2] + bx, v11 = acc[i * 4 + j][3] + by;
            if (!isV) {
                *(__half2*)&Ch[(size_t)r * 1024 + c] = __floats2half2_rn(v00, v01);
                *(__half2*)&Ch[(size_t)(r + 8) * 1024 + c] = __floats2half2_rn(v10, v11);
            } else {
                int bb = r >> 10, s = r & 1023;
                size_t base = ((size_t)(bb * 1024 + c)) * 1024;
                g_VT[base + s] = __float2half(v00);
                g_VT[base + 1024 + s] = __float2half(v01);
                g_VT[base + s + 8] = __float2half(v10);
                g_VT[base + 1024 + s + 8] = __float2half(v11);
            }
        }
    }
}

// ============ FP16 per-head A@B^T (c2p_att / p2c_att), g-major fp16 output ===
// tile 128(g) x 128(p), 256 threads (8 warps: 4m x 2n), K=64 -> 4 m16n8k16.
#define ABH 72

__global__ __launch_bounds__(256) void gemm_abT_f16() {
    int z = blockIdx.z;
    int h = z & 15;
    const __half* Ap = (z < 16) ? g_Q : g_K;
    const __half* Bp = (z < 16) ? g_PK : g_PQ;
    __half* Cp = (z < 16) ? g_c2p : g_p2c;

    extern __shared__ __half smh[];
    __half* As = smh;              // [128][72]
    __half* Bs = smh + 128 * ABH;  // [128][72]

    int tid = threadIdx.x;
    int lane = tid & 31, wid = tid >> 5;
    int qd = lane & 3, g = lane >> 2;
    int wm = (wid >> 1) * 32, wn = (wid & 1) * 64;
    int r0 = blockIdx.y * 128, p0 = blockIdx.x * 128;

    #pragma unroll
    for (int it = 0; it < 8; it++) {
        int idx = tid + it * 256;
        int row = idx >> 4, q = (idx & 15) * 4;
        *(uint2*)&As[row * ABH + q] = *(const uint2*)&Ap[(size_t)(r0 + row) * 1024 + h * 64 + q];
        *(uint2*)&Bs[row * ABH + q] = *(const uint2*)&Bp[(size_t)(p0 + row) * 1024 + h * 64 + q];
    }
    __syncthreads();

    float acc[16][4];
    #pragma unroll
    for (int t = 0; t < 16; t++)
        #pragma unroll
        for (int j = 0; j < 4; j++) acc[t][j] = 0.0f;

    #pragma unroll
    for (int s = 0; s < 4; s++) {
        int kb = s * 16 + 2 * qd;
        uint32_t af[2][4], bf[8][2];
        #pragma unroll
        for (int i = 0; i < 2; i++) {
            int r = wm + i * 16 + g;
            af[i][0] = *(uint32_t*)&As[r * ABH + kb];
            af[i][1] = *(uint32_t*)&As[(r + 8) * ABH + kb];
            af[i][2] = *(uint32_t*)&As[r * ABH + kb + 8];
            af[i][3] = *(uint32_t*)&As[(r + 8) * ABH + kb + 8];
        }
        #pragma unroll
        for (int j = 0; j < 8; j++) {
            int p = wn + j * 8 + g;
            bf[j][0] = *(uint32_t*)&Bs[p * ABH + kb];
            bf[j][1] = *(uint32_t*)&Bs[p * ABH + kb + 8];
        }
        #pragma unroll
        for (int i = 0; i < 2; i++)
            #pragma unroll
            for (int j = 0; j < 8; j++)
                mma_f16(acc[i * 8 + j], af[i], bf[j]);
    }

    #pragma unroll
    for (int i = 0; i < 2; i++) {
        #pragma unroll
        for (int j = 0; j < 8; j++) {
            int r = r0 + wm + i * 16 + g;
            int c = p0 + wn + j * 8 + 2 * qd;
            *(__half2*)&Cp[((size_t)h * (NBATCH * SEQ) + r) * POS2 + c] =
                __floats2half2_rn(acc[i * 8 + j][0], acc[i * 8 + j][1]);
            *(__half2*)&Cp[((size_t)h * (NBATCH * SEQ) + r + 8) * POS2 + c] =
                __floats2half2_rn(acc[i * 8 + j][2], acc[i * 8 + j][3]);
        }
    }
}

// ================= FP16 tensor-core flash attention ==========================
// 128(q) x 64(k) tiles, 256 threads, 2 CTAs/SM; m16n8k16; P feeds PV directly.
#define AQH 72

__global__ __launch_bounds__(256, 2) void attn_tc_kernel(float* __restrict__ out) {
    extern __shared__ __half smh[];
    __half* Qs = smh;               // [128][72]
    __half* Ks = Qs + 128 * AQH;    // [64][72]   ([n][k])
    __half* Vt = Ks + 64 * AQH;     // [64][72]   ([d][k])

    int tid = threadIdx.x;
    int lane = tid & 31, wid = tid >> 5;
    int qd = lane & 3, g = lane >> 2;
    int bh = blockIdx.y;
    int b = bh >> 4, h = bh & 15;
    int q0 = blockIdx.x * 128;

    // load Q tile: 128 rows x 64 halves
    #pragma unroll
    for (int it = 0; it < 8; it++) {
        int idx = tid + it * 256;
        int row = idx >> 4, q = (idx & 15) * 4;
        *(uint2*)&Qs[row * AQH + q] = *(const uint2*)&g_Q[(size_t)(b * SEQ + q0 + row) * 1024 + h * 64 + q];
    }

    int r0l = wid * 16 + g;
    int row0 = q0 + r0l, row1 = row0 + 8;
    const __half* c2p0 = &g_c2p[((size_t)h * (NBATCH * SEQ) + b * SEQ + row0) * POS2];
    const __half* c2p1 = &g_c2p[((size_t)h * (NBATCH * SEQ) + b * SEQ + row1) * POS2];
    const __half* p2cb = &g_p2c[((size_t)h * (NBATCH * SEQ) + b * SEQ) * POS2];
    const unsigned* pm0 = &g_pmask[(size_t)(b * SEQ + row0) * 32];
    const unsigned* pm1 = &g_pmask[(size_t)(b * SEQ + row1) * 32];

    float m_run0 = -FLT_MAX, m_run1 = -FLT_MAX, l_run0 = 0.0f, l_run1 = 0.0f;
    float O[8][4];
    #pragma unroll
    for (int f = 0; f < 8; f++)
        #pragma unroll
        for (int j = 0; j < 4; j++) O[f][j] = 0.0f;

    const float inv_scale = 0.07216878364870323f; // 1/sqrt(64*3)

    for (int k0 = 0; k0 < SEQ; k0 += 64) {
        __syncthreads();
        // K rows [n][k-chunk d], VT rows [d][k window]
        #pragma unroll
        for (int it = 0; it < 4; it++) {
            int idx = tid + it * 256;
            int row = idx >> 4, q = (idx & 15) * 4;
            *(uint2*)&Ks[row * AQH + q] = *(const uint2*)&g_K[(size_t)(b * SEQ + k0 + row) * 1024 + h * 64 + q];
            *(uint2*)&Vt[row * AQH + q] = *(const uint2*)&g_VT[((size_t)(b * 1024 + h * 64 + row)) * 1024 + k0 + q];
        }
        __syncthreads();

        // ---- S = Q K^T (4 fp16 mma steps)
        float sa[8][4];
        #pragma unroll
        for (int f = 0; f < 8; f++)
            #pragma unroll
            for (int j = 0; j < 4; j++) sa[f][j] = 0.0f;

        #pragma unroll
        for (int s = 0; s < 4; s++) {
            int kb = s * 16 + 2 * qd;
            uint32_t a[4];
            a[0] = *(uint32_t*)&Qs[r0l * AQH + kb];
            a[1] = *(uint32_t*)&Qs[(r0l + 8) * AQH + kb];
            a[2] = *(uint32_t*)&Qs[r0l * AQH + kb + 8];
            a[3] = *(uint32_t*)&Qs[(r0l + 8) * AQH + kb + 8];
            #pragma unroll
            for (int nf = 0; nf < 8; nf++) {
                int n = nf * 8 + g;
                uint32_t bfr[2];
                bfr[0] = *(uint32_t*)&Ks[n * AQH + kb];
                bfr[1] = *(uint32_t*)&Ks[n * AQH + kb + 8];
                mma_f16(sa[nf], a, bfr);
            }
        }

        // ---- masks (bit-packed)
        unsigned m0a = pm0[k0 >> 5], m0b = pm0[(k0 >> 5) + 1];
        unsigned m1a = pm1[k0 >> 5], m1b = pm1[(k0 >> 5) + 1];

        // ---- bias + scale + mask (register-resident scattered fp16 gathers)
        float s0max = -FLT_MAX, s1max = -FLT_MAX;
        #pragma unroll
        for (int nf = 0; nf < 8; nf++) {
            #pragma unroll
            for (int j = 0; j < 2; j++) {
                int kl = nf * 8 + 2 * qd + j;
                int kg = k0 + kl;
                int d0 = row0 - kg + 1023;
                int2 i0 = __ldg(&g_idx2[d0]);
                int2 i1 = __ldg(&g_idx2[d0 + 8]);
                float b0 = __half2float(__ldg(&c2p0[i0.x])) + __half2float(__ldg(&p2cb[(size_t)kg * POS2 + i0.y]));
                float b1 = __half2float(__ldg(&c2p1[i1.x])) + __half2float(__ldg(&p2cb[(size_t)kg * POS2 + i1.y]));
                float v0 = (sa[nf][j] + b0) * inv_scale;
                float v1 = (sa[nf][j + 2] + b1) * inv_scale;
                unsigned w0 = (kl & 32) ? m0b : m0a;
                unsigned w1 = (kl & 32) ? m1b : m1a;
                v0 = ((w0 >> (kl & 31)) & 1u) ? v0 : -FLT_MAX;
                v1 = ((w1 >> (kl & 31)) & 1u) ? v1 : -FLT_MAX;
                sa[nf][j] = v0; sa[nf][j + 2] = v1;
                s0max = fmaxf(s0max, v0); s1max = fmaxf(s1max, v1);
            }
        }

        // ---- online softmax (row over quad)
        s0max = fmaxf(s0max, __shfl_xor_sync(0xffffffffu, s0max, 1));
        s0max = fmaxf(s0max, __shfl_xor_sync(0xffffffffu, s0max, 2));
        s1max = fmaxf(s1max, __shfl_xor_sync(0xffffffffu, s1max, 1));
        s1max = fmaxf(s1max, __shfl_xor_sync(0xffffffffu, s1max, 2));
        float m0n = fmaxf(m_run0, s0max), m1n = fmaxf(m_run1, s1max);
        float a0 = __expf(m_run0 - m0n), a1 = __expf(m_run1 - m1n);
        float psum0 = 0.0f, psum1 = 0.0f;
        #pragma unroll
        for (int nf = 0; nf < 8; nf++) {
            sa[nf][0] = __expf(sa[nf][0] - m0n);
            sa[nf][1] = __expf(sa[nf][1] - m0n);
            sa[nf][2] = __expf(sa[nf][2] - m1n);
            sa[nf][3] = __expf(sa[nf][3] - m1n);
            psum0 += sa[nf][0] + sa[nf][1];
            psum1 += sa[nf][2] + sa[nf][3];
        }
        psum0 += __shfl_xor_sync(0xffffffffu, psum0, 1);
        psum0 += __shfl_xor_sync(0xffffffffu, psum0, 2);
        psum1 += __shfl_xor_sync(0xffffffffu, psum1, 1);
        psum1 += __shfl_xor_sync(0xffffffffu, psum1, 2);
        l_run0 = l_run0 * a0 + psum0;
        l_run1 = l_run1 * a1 + psum1;
        m_run0 = m0n; m_run1 = m1n;
        #pragma unroll
        for (int f = 0; f < 8; f++) {
            O[f][0] *= a0; O[f][1] *= a0; O[f][2] *= a1; O[f][3] *= a1;
        }

        // ---- O += P V : C-fragment of S IS the A-fragment of PV (fp16 trick)
        #pragma unroll
        for (int s = 0; s < 4; s++) {
            uint32_t a[4];
            a[0] = packh2(sa[2 * s][0],     sa[2 * s][1]);
            a[1] = packh2(sa[2 * s][2],     sa[2 * s][3]);
            a[2] = packh2(sa[2 * s + 1][0], sa[2 * s + 1][1]);
            a[3] = packh2(sa[2 * s + 1][2], sa[2 * s + 1][3]);
            int kb = s * 16 + 2 * qd;
            #pragma unroll
            for (int nf = 0; nf < 8; nf++) {
                int n = nf * 8 + g;
                uint32_t bfr[2];
                bfr[0] = *(uint32_t*)&Vt[n * AQH + kb];
                bfr[1] = *(uint32_t*)&Vt[n * AQH + kb + 8];
                mma_f16(O[nf], a, bfr);
            }
        }
    }

    // ---- epilogue
    float invl0 = (m_run0 == -FLT_MAX) ? 0.0f : (1.0f / l_run0);
    float invl1 = (m_run1 == -FLT_MAX) ? 0.0f : (1.0f / l_run1);
    #pragma unroll
    for (int nf = 0; nf < 8; nf++) {
        int d = nf * 8 + 2 * qd;
        float2 o0 = {O[nf][0] * invl0, O[nf][1] * invl0};
        *(float2*)&out[(size_t)(b * SEQ + row0) * 1024 + h * 64 + d] = o0;
        float2 o1 = {O[nf][2] * invl1, O[nf][3] * invl1};
        *(float2*)&out[(size_t)(b * SEQ + row1) * 1024 + h * 64 + d] = o1;
    }
}

// ---------------- launch ----------------------------------------------------
extern "C" void kernel_launch(void* const* d_in, const int* in_sizes, int n_in,
                              void* d_out, int out_size) {
    const float* hidden = (const float*)d_in[0];
    const int*   mask   = (const int*)d_in[1];
    const float* rel    = (const float*)d_in[2];
    const float* Wq     = (const float*)d_in[3];
    const float* bq     = (const float*)d_in[4];
    const float* Wk     = (const float*)d_in[5];
    const float* bk     = (const float*)d_in[6];
    const float* Wv     = (const float*)d_in[7];
    const float* bv     = (const float*)d_in[8];
    float* out = (float*)d_out;

    init_tables_kernel<<<8, 256>>>();
    pack_mask_kernel<<<NBATCH * SEQ * SEQ / 256, 256>>>(mask);

    int smem_qkv = (2 * QKV_ABUF + 2 * QKV_BBUF) * (int)sizeof(uint32_t);
    cudaFuncSetAttribute(gemm_proj_tf32, cudaFuncAttributeMaxDynamicSharedMemorySize, smem_qkv);
    gemm_proj_tf32<<<dim3(8, 20, 3), 256, smem_qkv>>>(
        hidden, rel, Wq, Wk, Wv, bq, bk, bv);

    int smem_abt = (2 * 128 * ABH) * (int)sizeof(__half);
    cudaFuncSetAttribute(gemm_abT_f16, cudaFuncAttributeMaxDynamicSharedMemorySize, smem_abt);
    gemm_abT_f16<<<dim3(POS2 / 128, 16, 32), 256, smem_abt>>>();

    int smem_attn = ((128 + 64 + 64) * AQH) * (int)sizeof(__half);
    cudaFuncSetAttribute(attn_tc_kernel, cudaFuncAttributeMaxDynamicSharedMemorySize, smem_attn);
    attn_tc_kernel<<<dim3(SEQ / 128, NBATCH * NHEAD), 256, smem_attn>>>(out);
}

// round 9
// speedup vs baseline: 2.3766x; 1.1040x over previous
#include <cuda_runtime.h>
#include <cuda_fp16.h>
#include <math.h>
#include <float.h>
#include <stdint.h>

#define SEQ    1024
#define DMODEL 1024
#define NHEAD  16
#define DHEAD  64
#define NBATCH 2
#define POS2   512

// ---------------- scratch ----------------------------------------------------
__device__ __half g_Hh[NBATCH * SEQ * DMODEL];           // hidden fp16
__device__ __half g_Rh[POS2 * DMODEL];                   // rel fp16
__device__ __half g_WT[3 * DMODEL * DMODEL];             // W^T fp16 [z][n][k]
__device__ __half g_Q[NBATCH * SEQ * DMODEL];
__device__ __half g_K[NBATCH * SEQ * DMODEL];
__device__ __half g_VT[NBATCH * DMODEL * SEQ];           // [b*1024+ch][s]
__device__ __half g_PQ[POS2 * DMODEL];
__device__ __half g_PK[POS2 * DMODEL];
__device__ __half g_c2p[NHEAD * NBATCH * SEQ * POS2];    // [h][g][bucket]
__device__ __half g_p2c[NHEAD * NBATCH * SEQ * POS2];    // [h][g][bucket]
__device__ ushort2 g_idx2s[2047];                        // (idxC, idxP)
__device__ unsigned g_pmask[NBATCH * SEQ * (SEQ / 32)];

// ---------------- helpers ----------------------------------------------------
__device__ __forceinline__ void mma_f16(float c[4], const uint32_t a[4], const uint32_t b[2]) {
    asm volatile(
        "mma.sync.aligned.m16n8k16.row.col.f32.f16.f16.f32 "
        "{%0,%1,%2,%3}, {%4,%5,%6,%7}, {%8,%9}, {%0,%1,%2,%3};"
        : "+f"(c[0]), "+f"(c[1]), "+f"(c[2]), "+f"(c[3])
        : "r"(a[0]), "r"(a[1]), "r"(a[2]), "r"(a[3]), "r"(b[0]), "r"(b[1]));
}
__device__ __forceinline__ uint32_t packh2(float lo, float hi) {
    __half2 h = __floats2half2_rn(lo, hi);
    return *(uint32_t*)&h;
}

// ---------------- pre-passes --------------------------------------------------
__global__ void convert_f2h(const float* __restrict__ src, __half* __restrict__ dst, int n4) {
    int i = blockIdx.x * 256 + threadIdx.x;
    if (i < n4) {
        float4 v = ((const float4*)src)[i];
        ((__half2*)dst)[2 * i]     = __floats2half2_rn(v.x, v.y);
        ((__half2*)dst)[2 * i + 1] = __floats2half2_rn(v.z, v.w);
    }
}

__global__ void transpose_w(const float* __restrict__ W0, const float* __restrict__ W1,
                            const float* __restrict__ W2) {
    __shared__ float t[32][33];
    const float* W = (blockIdx.z == 0) ? W0 : (blockIdx.z == 1) ? W1 : W2;
    __half* D = g_WT + (size_t)blockIdx.z * DMODEL * DMODEL;
    int x = blockIdx.x * 32 + threadIdx.x;
    int y0 = blockIdx.y * 32 + threadIdx.y;
    #pragma unroll
    for (int i = 0; i < 32; i += 8)
        t[threadIdx.y + i][threadIdx.x] = W[(size_t)(y0 + i) * 1024 + x];
    __syncthreads();
    int nx = blockIdx.y * 32 + threadIdx.x;
    int ny = blockIdx.x * 32 + threadIdx.y;
    #pragma unroll
    for (int i = 0; i < 32; i += 8)
        D[(size_t)(ny + i) * 1024 + nx] = __float2half(t[threadIdx.x][threadIdx.y + i]);
}

// ---------------- log-bucket tables ------------------------------------------
__device__ __forceinline__ int log_bucket(int rel) {
    const int mid = 128;
    float absp;
    if (rel < mid && rel > -mid) absp = (float)(mid - 1);
    else absp = fabsf((float)rel);
    if (absp <= (float)mid) return rel;
    float lp = ceilf(logf(absp / 128.0f) / 1.3843393291f * 127.0f) + 128.0f;
    float sgn = (rel > 0) ? 1.0f : ((rel < 0) ? -1.0f : 0.0f);
    return (int)(lp * sgn);
}
__global__ void init_tables_kernel() {
    int t = blockIdx.x * blockDim.x + threadIdx.x;
    if (t < 2047) {
        int delta = t - 1023;
        int bC = log_bucket(delta);
        int bP = log_bucket(-delta);
        ushort2 v;
        v.x = (unsigned short)min(max(bC + 256, 0), 511);
        v.y = (unsigned short)min(max(-bP + 256, 0), 511);
        g_idx2s[t] = v;
    }
}

// ---------------- mask bit-pack ----------------------------------------------
__global__ void pack_mask_kernel(const int* __restrict__ mask) {
    int idx = blockIdx.x * 256 + threadIdx.x;
    int v = mask[idx];
    unsigned bal = __ballot_sync(0xffffffffu, v != 0);
    if ((threadIdx.x & 31) == 0) g_pmask[idx >> 5] = bal;
}

// ================= FP16 GEMM: projections ====================================
// 128x128 tile, K-chunk 32 (2 k-steps), 256 threads (8 warps: 2m x 4n),
// double-buffered smem, A from g_Hh/g_Rh, B from g_WT (both [row][k] fp16).
#define PAS 40
#define PBUF (128 * PAS)

__global__ __launch_bounds__(256) void gemm_proj_f16(
    const float* __restrict__ bq, const float* __restrict__ bk, const float* __restrict__ bv) {

    int z = blockIdx.z;
    int y = blockIdx.y;
    const __half* A;
    __half* Ch = nullptr;
    bool isV = false;
    int m0;
    if (y < 16) {
        A = g_Hh; m0 = y * 128;
        if (z == 0) Ch = g_Q; else if (z == 1) Ch = g_K; else isV = true;
    } else {
        if (z == 2) return;
        A = g_Rh; m0 = (y - 16) * 128;
        Ch = (z == 0) ? g_PQ : g_PK;
    }
    const __half* WT = g_WT + (size_t)z * DMODEL * DMODEL;
    const float* bias = (z == 0) ? bq : (z == 1) ? bk : bv;

    extern __shared__ __half smh[];
    __half* As = smh;              // [2][128][40]
    __half* Bs = smh + 2 * PBUF;   // [2][128][40]

    int tid = threadIdx.x;
    int lane = tid & 31, wid = tid >> 5;
    int qd = lane & 3, g = lane >> 2;
    int wm = (wid >> 2) * 64, wn = (wid & 3) * 32;
    int n0 = blockIdx.x * 128;

    int lrow = tid >> 3, lcol = (tid & 7) * 4;

    uint2 ra[4], rb[4];
    float acc[16][4];
    #pragma unroll
    for (int t = 0; t < 16; t++)
        #pragma unroll
        for (int j = 0; j < 4; j++) acc[t][j] = 0.0f;

    #pragma unroll
    for (int p = 0; p < 4; p++) {
        ra[p] = *(const uint2*)&A[(size_t)(m0 + lrow + p * 32) * 1024 + lcol];
        rb[p] = *(const uint2*)&WT[(size_t)(n0 + lrow + p * 32) * 1024 + lcol];
    }
    #pragma unroll
    for (int p = 0; p < 4; p++) {
        *(uint2*)&As[(lrow + p * 32) * PAS + lcol] = ra[p];
        *(uint2*)&Bs[(lrow + p * 32) * PAS + lcol] = rb[p];
    }
    __syncthreads();

    int buf = 0;
    for (int kk = 32; kk <= 1024; kk += 32) {
        if (kk < 1024) {
            #pragma unroll
            for (int p = 0; p < 4; p++) {
                ra[p] = *(const uint2*)&A[(size_t)(m0 + lrow + p * 32) * 1024 + kk + lcol];
                rb[p] = *(const uint2*)&WT[(size_t)(n0 + lrow + p * 32) * 1024 + kk + lcol];
            }
        }
        const __half* Ab = &As[buf * PBUF];
        const __half* Bb = &Bs[buf * PBUF];
        #pragma unroll
        for (int ks = 0; ks < 2; ks++) {
            int kb = ks * 16 + 2 * qd;
            uint32_t af[4][4], bf[4][2];
            #pragma unroll
            for (int i = 0; i < 4; i++) {
                int r = wm + i * 16 + g;
                af[i][0] = *(const uint32_t*)&Ab[r * PAS + kb];
                af[i][1] = *(const uint32_t*)&Ab[(r + 8) * PAS + kb];
                af[i][2] = *(const uint32_t*)&Ab[r * PAS + kb + 8];
                af[i][3] = *(const uint32_t*)&Ab[(r + 8) * PAS + kb + 8];
            }
            #pragma unroll
            for (int j = 0; j < 4; j++) {
                int n = wn + j * 8 + g;
                bf[j][0] = *(const uint32_t*)&Bb[n * PAS + kb];
                bf[j][1] = *(const uint32_t*)&Bb[n * PAS + kb + 8];
            }
            #pragma unroll
            for (int i = 0; i < 4; i++)
                #pragma unroll
                for (int j = 0; j < 4; j++)
                    mma_f16(acc[i * 4 + j], af[i], bf[j]);
        }
        __syncthreads();
        if (kk < 1024) {
            buf ^= 1;
            #pragma unroll
            for (int p = 0; p < 4; p++) {
                *(uint2*)&As[buf * PBUF + (lrow + p * 32) * PAS + lcol] = ra[p];
                *(uint2*)&Bs[buf * PBUF + (lrow + p * 32) * PAS + lcol] = rb[p];
            }
            __syncthreads();
        }
    }

    #pragma unroll
    for (int i = 0; i < 4; i++) {
        #pragma unroll
        for (int j = 0; j < 4; j++) {
            int r = m0 + wm + i * 16 + g;
            int c = n0 + wn + j * 8 + 2 * qd;
            float bx = bias[c], by = bias[c + 1];
            float v00 = acc[i * 4 + j][0] + bx, v01 = acc[i * 4 + j][1] + by;
            float v10 = acc[i * 4 + j][2] + bx, v11 = acc[i * 4 + j][3] + by;
            if (!isV) {
                *(__half2*)&Ch[(size_t)r * 1024 + c] = __floats2half2_rn(v00, v01);
                *(__half2*)&Ch[(size_t)(r + 8) * 1024 + c] = __floats2half2_rn(v10, v11);
            } else {
                int bb = r >> 10, s = r & 1023;
                size_t base = ((size_t)(bb * 1024 + c)) * 1024;
                g_VT[base + s] = __float2half(v00);
                g_VT[base + 1024 + s] = __float2half(v01);
                g_VT[base + s + 8] = __float2half(v10);
                g_VT[base + 1024 + s + 8] = __float2half(v11);
            }
        }
    }
}

// ============ FP16 per-head A@B^T (c2p_att / p2c_att), g-major fp16 output ===
#define ABH 72

__global__ __launch_bounds__(256) void gemm_abT_f16() {
    int z = blockIdx.z;
    int h = z & 15;
    const __half* Ap = (z < 16) ? g_Q : g_K;
    const __half* Bp = (z < 16) ? g_PK : g_PQ;
    __half* Cp = (z < 16) ? g_c2p : g_p2c;

    extern __shared__ __half smh[];
    __half* As = smh;              // [128][72]
    __half* Bs = smh + 128 * ABH;  // [128][72]

    int tid = threadIdx.x;
    int lane = tid & 31, wid = tid >> 5;
    int qd = lane & 3, g = lane >> 2;
    int wm = (wid >> 1) * 32, wn = (wid & 1) * 64;
    int r0 = blockIdx.y * 128, p0 = blockIdx.x * 128;

    #pragma unroll
    for (int it = 0; it < 8; it++) {
        int idx = tid + it * 256;
        int row = idx >> 4, q = (idx & 15) * 4;
        *(uint2*)&As[row * ABH + q] = *(const uint2*)&Ap[(size_t)(r0 + row) * 1024 + h * 64 + q];
        *(uint2*)&Bs[row * ABH + q] = *(const uint2*)&Bp[(size_t)(p0 + row) * 1024 + h * 64 + q];
    }
    __syncthreads();

    float acc[16][4];
    #pragma unroll
    for (int t = 0; t < 16; t++)
        #pragma unroll
        for (int j = 0; j < 4; j++) acc[t][j] = 0.0f;

    #pragma unroll
    for (int s = 0; s < 4; s++) {
        int kb = s * 16 + 2 * qd;
        uint32_t af[2][4], bf[8][2];
        #pragma unroll
        for (int i = 0; i < 2; i++) {
            int r = wm + i * 16 + g;
            af[i][0] = *(uint32_t*)&As[r * ABH + kb];
            af[i][1] = *(uint32_t*)&As[(r + 8) * ABH + kb];
            af[i][2] = *(uint32_t*)&As[r * ABH + kb + 8];
            af[i][3] = *(uint32_t*)&As[(r + 8) * ABH + kb + 8];
        }
        #pragma unroll
        for (int j = 0; j < 8; j++) {
            int p = wn + j * 8 + g;
            bf[j][0] = *(uint32_t*)&Bs[p * ABH + kb];
            bf[j][1] = *(uint32_t*)&Bs[p * ABH + kb + 8];
        }
        #pragma unroll
        for (int i = 0; i < 2; i++)
            #pragma unroll
            for (int j = 0; j < 8; j++)
                mma_f16(acc[i * 8 + j], af[i], bf[j]);
    }

    #pragma unroll
    for (int i = 0; i < 2; i++) {
        #pragma unroll
        for (int j = 0; j < 8; j++) {
            int r = r0 + wm + i * 16 + g;
            int c = p0 + wn + j * 8 + 2 * qd;
            *(__half2*)&Cp[((size_t)h * (NBATCH * SEQ) + r) * POS2 + c] =
                __floats2half2_rn(acc[i * 8 + j][0], acc[i * 8 + j][1]);
            *(__half2*)&Cp[((size_t)h * (NBATCH * SEQ) + r + 8) * POS2 + c] =
                __floats2half2_rn(acc[i * 8 + j][2], acc[i * 8 + j][3]);
        }
    }
}

// ================= FP16 tensor-core flash attention ==========================
// 128(q) x 64(k) tiles, 256 threads, 2 CTAs/SM; idx table cached in smem.
#define AQH 72

__global__ __launch_bounds__(256, 2) void attn_tc_kernel(float* __restrict__ out) {
    extern __shared__ __half smh[];
    __half* Qs = smh;               // [128][72]
    __half* Ks = Qs + 128 * AQH;    // [64][72]
    __half* Vt = Ks + 64 * AQH;     // [64][72]
    ushort2* idxs = (ushort2*)(Vt + 64 * AQH);  // [1151]

    int tid = threadIdx.x;
    int lane = tid & 31, wid = tid >> 5;
    int qd = lane & 3, g = lane >> 2;
    int bh = blockIdx.y;
    int b = bh >> 4, h = bh & 15;
    int q0 = blockIdx.x * 128;

    // load Q tile + idx slice
    #pragma unroll
    for (int it = 0; it < 8; it++) {
        int idx = tid + it * 256;
        int row = idx >> 4, q = (idx & 15) * 4;
        *(uint2*)&Qs[row * AQH + q] = *(const uint2*)&g_Q[(size_t)(b * SEQ + q0 + row) * 1024 + h * 64 + q];
    }
    for (int t = tid; t < 1151; t += 256) idxs[t] = g_idx2s[q0 + t];

    int r0l = wid * 16 + g;
    int row0 = q0 + r0l, row1 = row0 + 8;
    const __half* c2p0 = &g_c2p[((size_t)h * (NBATCH * SEQ) + b * SEQ + row0) * POS2];
    const __half* c2p1 = &g_c2p[((size_t)h * (NBATCH * SEQ) + b * SEQ + row1) * POS2];
    const __half* p2cb = &g_p2c[((size_t)h * (NBATCH * SEQ) + b * SEQ) * POS2];
    const unsigned* pm0 = &g_pmask[(size_t)(b * SEQ + row0) * 32];
    const unsigned* pm1 = &g_pmask[(size_t)(b * SEQ + row1) * 32];

    float m_run0 = -FLT_MAX, m_run1 = -FLT_MAX, l_run0 = 0.0f, l_run1 = 0.0f;
    float O[8][4];
    #pragma unroll
    for (int f = 0; f < 8; f++)
        #pragma unroll
        for (int j = 0; j < 4; j++) O[f][j] = 0.0f;

    const float inv_scale = 0.07216878364870323f; // 1/sqrt(64*3)

    for (int k0 = 0; k0 < SEQ; k0 += 64) {
        __syncthreads();
        #pragma unroll
        for (int it = 0; it < 4; it++) {
            int idx = tid + it * 256;
            int row = idx >> 4, q = (idx & 15) * 4;
            *(uint2*)&Ks[row * AQH + q] = *(const uint2*)&g_K[(size_t)(b * SEQ + k0 + row) * 1024 + h * 64 + q];
            *(uint2*)&Vt[row * AQH + q] = *(const uint2*)&g_VT[((size_t)(b * 1024 + h * 64 + row)) * 1024 + k0 + q];
        }
        __syncthreads();

        // ---- S = Q K^T
        float sa[8][4];
        #pragma unroll
        for (int f = 0; f < 8; f++)
            #pragma unroll
            for (int j = 0; j < 4; j++) sa[f][j] = 0.0f;

        #pragma unroll
        for (int s = 0; s < 4; s++) {
            int kb = s * 16 + 2 * qd;
            uint32_t a[4];
            a[0] = *(uint32_t*)&Qs[r0l * AQH + kb];
            a[1] = *(uint32_t*)&Qs[(r0l + 8) * AQH + kb];
            a[2] = *(uint32_t*)&Qs[r0l * AQH + kb + 8];
            a[3] = *(uint32_t*)&Qs[(r0l + 8) * AQH + kb + 8];
            #pragma unroll
            for (int nf = 0; nf < 8; nf++) {
                int n = nf * 8 + g;
                uint32_t bfr[2];
                bfr[0] = *(uint32_t*)&Ks[n * AQH + kb];
                bfr[1] = *(uint32_t*)&Ks[n * AQH + kb + 8];
                mma_f16(sa[nf], a, bfr);
            }
        }

        // ---- masks (bit-packed)
        unsigned m0a = pm0[k0 >> 5], m0b = pm0[(k0 >> 5) + 1];
        unsigned m1a = pm1[k0 >> 5], m1b = pm1[(k0 >> 5) + 1];

        // ---- bias + scale + mask (idx from smem, bias gathers from gmem)
        float s0max = -FLT_MAX, s1max = -FLT_MAX;
        #pragma unroll
        for (int nf = 0; nf < 8; nf++) {
            #pragma unroll
            for (int j = 0; j < 2; j++) {
                int kl = nf * 8 + 2 * qd + j;
                int kg = k0 + kl;
                int li = r0l - kg + 1023;
                ushort2 i0 = idxs[li];
                ushort2 i1 = idxs[li + 8];
                float b0 = __half2float(__ldg(&c2p0[i0.x])) + __half2float(__ldg(&p2cb[(size_t)kg * POS2 + i0.y]));
                float b1 = __half2float(__ldg(&c2p1[i1.x])) + __half2float(__ldg(&p2cb[(size_t)kg * POS2 + i1.y]));
                float v0 = (sa[nf][j] + b0) * inv_scale;
                float v1 = (sa[nf][j + 2] + b1) * inv_scale;
                unsigned w0 = (kl & 32) ? m0b : m0a;
                unsigned w1 = (kl & 32) ? m1b : m1a;
                v0 = ((w0 >> (kl & 31)) & 1u) ? v0 : -FLT_MAX;
                v1 = ((w1 >> (kl & 31)) & 1u) ? v1 : -FLT_MAX;
                sa[nf][j] = v0; sa[nf][j + 2] = v1;
                s0max = fmaxf(s0max, v0); s1max = fmaxf(s1max, v1);
            }
        }

        // ---- online softmax (row over quad)
        s0max = fmaxf(s0max, __shfl_xor_sync(0xffffffffu, s0max, 1));
        s0max = fmaxf(s0max, __shfl_xor_sync(0xffffffffu, s0max, 2));
        s1max = fmaxf(s1max, __shfl_xor_sync(0xffffffffu, s1max, 1));
        s1max = fmaxf(s1max, __shfl_xor_sync(0xffffffffu, s1max, 2));
        float m0n = fmaxf(m_run0, s0max), m1n = fmaxf(m_run1, s1max);
        float a0 = __expf(m_run0 - m0n), a1 = __expf(m_run1 - m1n);
        float psum0 = 0.0f, psum1 = 0.0f;
        #pragma unroll
        for (int nf = 0; nf < 8; nf++) {
            sa[nf][0] = __expf(sa[nf][0] - m0n);
            sa[nf][1] = __expf(sa[nf][1] - m0n);
            sa[nf][2] = __expf(sa[nf][2] - m1n);
            sa[nf][3] = __expf(sa[nf][3] - m1n);
            psum0 += sa[nf][0] + sa[nf][1];
            psum1 += sa[nf][2] + sa[nf][3];
        }
        psum0 += __shfl_xor_sync(0xffffffffu, psum0, 1);
        psum0 += __shfl_xor_sync(0xffffffffu, psum0, 2);
        psum1 += __shfl_xor_sync(0xffffffffu, psum1, 1);
        psum1 += __shfl_xor_sync(0xffffffffu, psum1, 2);
        l_run0 = l_run0 * a0 + psum0;
        l_run1 = l_run1 * a1 + psum1;
        m_run0 = m0n; m_run1 = m1n;
        #pragma unroll
        for (int f = 0; f < 8; f++) {
            O[f][0] *= a0; O[f][1] *= a0; O[f][2] *= a1; O[f][3] *= a1;
        }

        // ---- O += P V (fp16 C->A fragment identity)
        #pragma unroll
        for (int s = 0; s < 4; s++) {
            uint32_t a[4];
            a[0] = packh2(sa[2 * s][0],     sa[2 * s][1]);
            a[1] = packh2(sa[2 * s][2],     sa[2 * s][3]);
            a[2] = packh2(sa[2 * s + 1][0], sa[2 * s + 1][1]);
            a[3] = packh2(sa[2 * s + 1][2], sa[2 * s + 1][3]);
            int kb = s * 16 + 2 * qd;
            #pragma unroll
            for (int nf = 0; nf < 8; nf++) {
                int n = nf * 8 + g;
                uint32_t bfr[2];
                bfr[0] = *(uint32_t*)&Vt[n * AQH + kb];
                bfr[1] = *(uint32_t*)&Vt[n * AQH + kb + 8];
                mma_f16(O[nf], a, bfr);
            }
        }
    }

    // ---- epilogue
    float invl0 = (m_run0 == -FLT_MAX) ? 0.0f : (1.0f / l_run0);
    float invl1 = (m_run1 == -FLT_MAX) ? 0.0f : (1.0f / l_run1);
    #pragma unroll
    for (int nf = 0; nf < 8; nf++) {
        int d = nf * 8 + 2 * qd;
        float2 o0 = {O[nf][0] * invl0, O[nf][1] * invl0};
        *(float2*)&out[(size_t)(b * SEQ + row0) * 1024 + h * 64 + d] = o0;
        float2 o1 = {O[nf][2] * invl1, O[nf][3] * invl1};
        *(float2*)&out[(size_t)(b * SEQ + row1) * 1024 + h * 64 + d] = o1;
    }
}

// ---------------- launch ----------------------------------------------------
extern "C" void kernel_launch(void* const* d_in, const int* in_sizes, int n_in,
                              void* d_out, int out_size) {
    const float* hidden = (const float*)d_in[0];
    const int*   mask   = (const int*)d_in[1];
    const float* rel    = (const float*)d_in[2];
    const float* Wq     = (const float*)d_in[3];
    const float* bq     = (const float*)d_in[4];
    const float* Wk     = (const float*)d_in[5];
    const float* bk     = (const float*)d_in[6];
    const float* Wv     = (const float*)d_in[7];
    const float* bv     = (const float*)d_in[8];
    float* out = (float*)d_out;

    __half *Hh, *Rh;
    cudaGetSymbolAddress((void**)&Hh, g_Hh);
    cudaGetSymbolAddress((void**)&Rh, g_Rh);

    init_tables_kernel<<<8, 256>>>();
    pack_mask_kernel<<<NBATCH * SEQ * SEQ / 256, 256>>>(mask);
    convert_f2h<<<(NBATCH * SEQ * DMODEL / 4 + 255) / 256, 256>>>(hidden, Hh, NBATCH * SEQ * DMODEL / 4);
    convert_f2h<<<(POS2 * DMODEL / 4 + 255) / 256, 256>>>(rel, Rh, POS2 * DMODEL / 4);
    transpose_w<<<dim3(32, 32, 3), dim3(32, 8)>>>(Wq, Wk, Wv);

    int smem_proj = 4 * PBUF * (int)sizeof(__half);
    cudaFuncSetAttribute(gemm_proj_f16, cudaFuncAttributeMaxDynamicSharedMemorySize, smem_proj);
    gemm_proj_f16<<<dim3(8, 20, 3), 256, smem_proj>>>(bq, bk, bv);

    int smem_abt = (2 * 128 * ABH) * (int)sizeof(__half);
    cudaFuncSetAttribute(gemm_abT_f16, cudaFuncAttributeMaxDynamicSharedMemorySize, smem_abt);
    gemm_abT_f16<<<dim3(POS2 / 128, 16, 32), 256, smem_abt>>>();

    int smem_attn = ((128 + 64 + 64) * AQH) * (int)sizeof(__half) + 1152 * (int)sizeof(ushort2);
    cudaFuncSetAttribute(attn_tc_kernel, cudaFuncAttributeMaxDynamicSharedMemorySize, smem_attn);
    attn_tc_kernel<<<dim3(SEQ / 128, NBATCH * NHEAD), 256, smem_attn>>>(out);
}